// round 5
// baseline (speedup 1.0000x reference)
#include <cuda_runtime.h>
#include <cuda_bf16.h>
#include <math_constants.h>
#include <cstdint>

#define NN_  8192
#define DIN_ 1024
#define DD_  256
#define KT_  30
#define KS_  45     // screening candidates per row
#define KA4_ 1024   // 4-term split row length (trunk operands)
#define KAX_ 4096   // 4-term split of x (K=1024)

// ---------------- scratch (static device globals: allocation-free) ----------
__device__ __nv_bfloat16 g_P[(size_t)NN_ * NN_];     // screening logits (bf16, 128 MB)
__device__ float g_eh[NN_ * DD_];
__device__ float g_et[NN_ * DD_];
__device__ float g_E1[NN_ * DD_];
__device__ float g_spill[NN_ * DD_];
__device__ __nv_bfloat16 g_Xbf [(size_t)NN_ * KAX_];  // 64 MB
__device__ __nv_bfloat16 g_h1b [(size_t)NN_ * KA4_];
__device__ __nv_bfloat16 g_hb  [(size_t)NN_ * KA4_];
__device__ __nv_bfloat16 g_ehs [(size_t)NN_ * DD_];   // hi-only, scaled (4 MB)
__device__ __nv_bfloat16 g_ets [(size_t)NN_ * DD_];   // hi-only (4 MB)
__device__ __nv_bfloat16 g_Ub  [(size_t)NN_ * KA4_];
__device__ __nv_bfloat16 g_Vb  [(size_t)NN_ * KA4_];
__device__ __nv_bfloat16 g_Wfc1b[(size_t)DD_ * KAX_];
__device__ __nv_bfloat16 g_Wfc2b[DD_ * KA4_];
__device__ __nv_bfloat16 g_Whdb [DD_ * KA4_];
__device__ __nv_bfloat16 g_Wtlb [DD_ * KA4_];
__device__ __nv_bfloat16 g_Wl1b [DD_ * KA4_];
__device__ __nv_bfloat16 g_Wl2b [DD_ * KA4_];
__device__ int   g_tI[NN_ * KS_];
__device__ float g_att[NN_];
__device__ float g_red[2];
__device__ float g_part[32 * DD_];

// =================== warp-MMA helpers (sm_80+, compute_103-safe) ============
__device__ __forceinline__ uint32_t smem_u32(const void* p) {
    uint32_t a;
    asm("{ .reg .u64 t; cvta.to.shared.u64 t, %1; cvt.u32.u64 %0, t; }" : "=r"(a) : "l"(p));
    return a;
}
#define SW128(off) ((off) ^ (((off) >> 3) & 0x70))
#define CP16(dst, src)    asm volatile("cp.async.cg.shared.global [%0], [%1], 16;" :: "r"(dst), "l"(src) : "memory")
#define CP_COMMIT()       asm volatile("cp.async.commit_group;" ::: "memory")

__device__ __forceinline__ void ldsm4(uint32_t* r, uint32_t addr) {
    asm volatile("ldmatrix.sync.aligned.m8n8.x4.shared.b16 {%0,%1,%2,%3}, [%4];"
        : "=r"(r[0]), "=r"(r[1]), "=r"(r[2]), "=r"(r[3]) : "r"(addr));
}
__device__ __forceinline__ void mma16816(float* d, const uint32_t* a, const uint32_t* b) {
    asm volatile("mma.sync.aligned.m16n8k16.row.col.f32.bf16.bf16.f32 "
        "{%0,%1,%2,%3}, {%4,%5,%6,%7}, {%8,%9}, {%0,%1,%2,%3};"
        : "+f"(d[0]), "+f"(d[1]), "+f"(d[2]), "+f"(d[3])
        : "r"(a[0]), "r"(a[1]), "r"(a[2]), "r"(a[3]), "r"(b[0]), "r"(b[1]));
}

// ---------------- input / weight split prep ---------------------------------
__global__ void __launch_bounds__(256) xsplit_kernel(const float* __restrict__ x,
                                                     __nv_bfloat16* __restrict__ X)
{
    const int r = blockIdx.x;
    #pragma unroll
    for (int q = 0; q < 4; q++) {
        const int c = threadIdx.x + q * 256;
        float v = x[(size_t)r * DIN_ + c];
        __nv_bfloat16 h = __float2bfloat16(v);
        __nv_bfloat16 l = __float2bfloat16(v - __bfloat162float(h));
        __nv_bfloat16* row = X + (size_t)r * KAX_;
        row[c] = h; row[DIN_ + c] = l; row[2*DIN_ + c] = h; row[3*DIN_ + c] = l;
    }
}
__global__ void __launch_bounds__(256) wprep_kernel(const float* __restrict__ W,
                                                    __nv_bfloat16* __restrict__ Wb, int K)
{
    const int k = blockIdx.x;
    const int n = threadIdx.x;
    float v = W[(size_t)k * DD_ + n];
    __nv_bfloat16 h = __float2bfloat16(v);
    __nv_bfloat16 l = __float2bfloat16(v - __bfloat162float(h));
    __nv_bfloat16* row = Wb + (size_t)n * (4 * K);
    row[k] = h; row[K + k] = h; row[2*K + k] = l; row[3*K + k] = l;
}

// ---------------- shared tile fill -------------------------------------------
__device__ __forceinline__ void tile_fill(uint32_t sbase, int kc, int bm, int bn,
    const __nv_bfloat16* __restrict__ Ag, const __nv_bfloat16* __restrict__ Bg,
    int tid, int Ka)
{
    #pragma unroll
    for (int i = 0; i < 4; i++) {
        int q = tid + i * 256;
        int row = q >> 3, c = q & 7;
        const __nv_bfloat16* src = Ag + (size_t)(bm * 128 + row) * Ka + kc * 64 + c * 8;
        CP16(sbase + SW128((uint32_t)(row * 128 + c * 16)), src);
    }
    #pragma unroll
    for (int i = 0; i < 4; i++) {
        int q = tid + i * 256;
        int row = q >> 3, c = q & 7;
        const __nv_bfloat16* src = Bg + (size_t)(bn * 128 + row) * Ka + kc * 64 + c * 8;
        CP16(sbase + 16384 + SW128((uint32_t)(row * 128 + c * 16)), src);
    }
}

// ---------------- MMA mainloop core (BM=BN=128, BK=64, 8 warps 4x2) ---------
#define MMA_STG 32768
struct MmaAcc { float a[2][8][4]; };

__device__ __forceinline__ void mma_mainloop(MmaAcc& A_, uint32_t sb, int nchunk,
    int bm, int bn, const __nv_bfloat16* Ag, const __nv_bfloat16* Bg, int Ka,
    int tid, int wid, int lane)
{
    const int wm = (wid & 3) * 32;
    const int wn = (wid >> 2) * 64;
    const int aRow = (lane & 15);
    const int aKb  = (lane >> 4) * 16;
    const int bRow = ((lane >> 4) << 3) + (lane & 7);
    const int bKb  = ((lane >> 3) & 1) * 16;

    tile_fill(sb, 0, bm, bn, Ag, Bg, tid, Ka);
    CP_COMMIT();

    for (int c = 0; c < nchunk; c++) {
        if (c + 1 < nchunk) {
            tile_fill(sb + ((c + 1) & 1) * MMA_STG, c + 1, bm, bn, Ag, Bg, tid, Ka);
            CP_COMMIT();
            asm volatile("cp.async.wait_group 1;" ::: "memory");
        } else {
            asm volatile("cp.async.wait_group 0;" ::: "memory");
        }
        __syncthreads();

        const uint32_t aB = sb + (c & 1) * MMA_STG;
        const uint32_t bB = aB + 16384;
        #pragma unroll
        for (int ks = 0; ks < 4; ks++) {
            uint32_t af[2][4];
            #pragma unroll
            for (int mt = 0; mt < 2; mt++) {
                int row = wm + mt * 16 + aRow;
                ldsm4(af[mt], aB + SW128((uint32_t)(row * 128 + ks * 32 + aKb)));
            }
            uint32_t bf[4][4];
            #pragma unroll
            for (int nt = 0; nt < 4; nt++) {
                int row = wn + nt * 16 + bRow;
                ldsm4(bf[nt], bB + SW128((uint32_t)(row * 128 + ks * 32 + bKb)));
            }
            #pragma unroll
            for (int mt = 0; mt < 2; mt++)
                #pragma unroll
                for (int n8 = 0; n8 < 8; n8++)
                    mma16816(A_.a[mt][n8], af[mt], &bf[n8 >> 1][(n8 & 1) * 2]);
        }
        __syncthreads();
    }
}

// ---------------- screening GEMM: P(bf16) = ehs @ ets^T (hi-only, K=256) ----
__global__ void __launch_bounds__(256, 2) attn_mma_kernel(
    const __nv_bfloat16* __restrict__ Ag, const __nv_bfloat16* __restrict__ Bg,
    __nv_bfloat16* __restrict__ P)
{
    extern __shared__ char smem[];
    const uint32_t sb = smem_u32(smem);
    const int tid = threadIdx.x, wid = tid >> 5, lane = tid & 31;
    const int bn = blockIdx.x, bm = blockIdx.y;

    MmaAcc acc;
    #pragma unroll
    for (int i = 0; i < 2; i++)
        #pragma unroll
        for (int j = 0; j < 8; j++)
            #pragma unroll
            for (int q = 0; q < 4; q++) acc.a[i][j][q] = 0.f;

    mma_mainloop(acc, sb, DD_ / 64, bm, bn, Ag, Bg, DD_, tid, wid, lane);

    const int wm = (wid & 3) * 32, wn = (wid >> 2) * 64;
    const int tig = lane & 3, gid = lane >> 2;
    #pragma unroll
    for (int mt = 0; mt < 2; mt++) {
        const int r0 = bm * 128 + wm + mt * 16 + gid;
        #pragma unroll
        for (int n8 = 0; n8 < 8; n8++) {
            const int cc = bn * 128 + wn + n8 * 8 + tig * 2;
            *reinterpret_cast<__nv_bfloat162*>(P + (size_t)r0 * NN_ + cc)
                = __float22bfloat162_rn(make_float2(acc.a[mt][n8][0], acc.a[mt][n8][1]));
            *reinterpret_cast<__nv_bfloat162*>(P + (size_t)(r0 + 8) * NN_ + cc)
                = __float22bfloat162_rn(make_float2(acc.a[mt][n8][2], acc.a[mt][n8][3]));
        }
    }
}

// ---------------- trunk GEMM with fused split epilogues ---------------------
// OSPL: 0 none, 1 A4 [h|l|h|l], 2 hi-only scaled, 3 hi-only
template<int OSPL, bool RELU, bool HASADD>
__global__ void __launch_bounds__(256, 2) mma_gemm_kernel(
    const __nv_bfloat16* __restrict__ Ag, const __nv_bfloat16* __restrict__ Bg,
    const float* __restrict__ bias, const float* __restrict__ addend,
    float* __restrict__ C, __nv_bfloat16* __restrict__ S, int Ka, float scale)
{
    extern __shared__ char smem[];
    const uint32_t sb = smem_u32(smem);
    const int tid = threadIdx.x, wid = tid >> 5, lane = tid & 31;
    const int bn = blockIdx.x, bm = blockIdx.y;

    MmaAcc acc;
    #pragma unroll
    for (int i = 0; i < 2; i++)
        #pragma unroll
        for (int j = 0; j < 8; j++)
            #pragma unroll
            for (int q = 0; q < 4; q++) acc.a[i][j][q] = 0.f;

    mma_mainloop(acc, sb, Ka / 64, bm, bn, Ag, Bg, Ka, tid, wid, lane);

    const int wm = (wid & 3) * 32, wn = (wid >> 2) * 64;
    const int tig = lane & 3, gid = lane >> 2;
    #pragma unroll
    for (int mt = 0; mt < 2; mt++) {
        #pragma unroll
        for (int n8 = 0; n8 < 8; n8++) {
            const int cc = bn * 128 + wn + n8 * 8 + tig * 2;
            #pragma unroll
            for (int hh = 0; hh < 2; hh++) {
                const int r = bm * 128 + wm + mt * 16 + gid + hh * 8;
                #pragma unroll
                for (int e = 0; e < 2; e++) {
                    const int c = cc + e;
                    float v = acc.a[mt][n8][hh * 2 + e] + bias[c];
                    if (RELU)   v = fmaxf(v, 0.f);
                    if (HASADD) v += addend[(size_t)r * DD_ + c];
                    if (C) C[(size_t)r * DD_ + c] = v;
                    if (OSPL == 1) {
                        __nv_bfloat16 h = __float2bfloat16(v);
                        __nv_bfloat16 l = __float2bfloat16(v - __bfloat162float(h));
                        __nv_bfloat16* row = S + (size_t)r * KA4_;
                        row[c] = h; row[DD_ + c] = l; row[2*DD_ + c] = h; row[3*DD_ + c] = l;
                    } else if (OSPL == 2) {
                        S[(size_t)r * DD_ + c] = __float2bfloat16(v * scale);
                    } else if (OSPL == 3) {
                        S[(size_t)r * DD_ + c] = __float2bfloat16(v);
                    }
                }
            }
        }
    }
}

// ---------------- per-row top-45 screening (indices only) --------------------
__global__ void __launch_bounds__(256) topk_kernel(const __nv_bfloat16* __restrict__ P,
                                                   int* __restrict__ tI)
{
    const int row  = blockIdx.x;
    const int tid  = threadIdx.x;
    const int lane = tid & 31, w = tid >> 5;
    const __nv_bfloat16* p = P + (size_t)row * NN_;

    float v[32];
    #pragma unroll
    for (int j = 0; j < 32; j++) v[j] = __bfloat162float(p[tid + j * 256]);

    __shared__ float sV[8];
    __shared__ int   sI[9];

    for (int it = 0; it < KS_; it++) {
        float bv = v[0]; int bj = 0;
        #pragma unroll
        for (int j = 1; j < 32; j++) if (v[j] > bv) { bv = v[j]; bj = j; }
        int bi = tid + bj * 256;
        #pragma unroll
        for (int off = 16; off; off >>= 1) {
            float ov = __shfl_xor_sync(0xffffffffu, bv, off);
            int   oi = __shfl_xor_sync(0xffffffffu, bi, off);
            if (ov > bv || (ov == bv && oi < bi)) { bv = ov; bi = oi; }
        }
        if (lane == 0) { sV[w] = bv; sI[w] = bi; }
        __syncthreads();
        if (tid == 0) {
            float Bv = sV[0]; int Bi = sI[0];
            #pragma unroll
            for (int q = 1; q < 8; q++)
                if (sV[q] > Bv || (sV[q] == Bv && sI[q] < Bi)) { Bv = sV[q]; Bi = sI[q]; }
            tI[row * KS_ + it] = Bi;
            sI[8] = Bi;
        }
        __syncthreads();
        const int win = sI[8];
        if ((win & 255) == tid) {
            const int jj = win >> 8;
            #pragma unroll
            for (int j = 0; j < 32; j++) if (j == jj) v[j] = -CUDART_INF_F;
        }
    }
}

// ---------------- fused rescore + exact top-30 + neighbor aggregation -------
__global__ void __launch_bounds__(256) cand_kernel(
    const float* __restrict__ eH, const float* __restrict__ eT,
    const int* __restrict__ tI,
    __nv_bfloat16* __restrict__ Ub, __nv_bfloat16* __restrict__ Vb)
{
    const int row  = blockIdx.x;
    const int d    = threadIdx.x;
    const int lane = d & 31, w = d >> 5;

    __shared__ float sNb[KS_][DD_];
    __shared__ float sEh[DD_];
    __shared__ float sVal[KS_];
    __shared__ int   sIdx[KS_];
    __shared__ int   sSel[KT_];
    __shared__ float sPr[KT_];
    __shared__ float sW[KT_];
    __shared__ float sKa[KT_];

    const float eh = eH[(size_t)row * DD_ + d];
    sEh[d] = eh;
    if (d < KS_) sIdx[d] = tI[row * KS_ + d];
    __syncthreads();

    // gather candidate rows + exact fp32 rescore
    for (int k = w; k < KS_; k += 8) {
        const float* src = eT + (size_t)sIdx[k] * DD_;
        float dot = 0.f;
        #pragma unroll
        for (int q = 0; q < 8; q++) {
            const int dd = lane + q * 32;
            const float nb = src[dd];
            sNb[k][dd] = nb;
            dot += sEh[dd] * nb;
        }
        #pragma unroll
        for (int off = 16; off; off >>= 1) dot += __shfl_xor_sync(0xffffffffu, dot, off);
        if (lane == 0) sVal[k] = dot * 0.0625f;
    }
    __syncthreads();

    // warp 0: exact top-30 of 45 (tie -> lower global index), then softmax
    if (d < 32) {
        float va = (d < KS_) ? sVal[d] : -CUDART_INF_F;
        float vb = (d + 32 < KS_) ? sVal[d + 32] : -CUDART_INF_F;
        int   ia = (d < KS_) ? sIdx[d] : 0x7fffffff;
        int   ib = (d + 32 < KS_) ? sIdx[d + 32] : 0x7fffffff;
        for (int it = 0; it < KT_; it++) {
            float bv; int bi, bs;
            if (vb > va || (vb == va && ib < ia)) { bv = vb; bi = ib; bs = d + 32; }
            else                                  { bv = va; bi = ia; bs = d; }
            #pragma unroll
            for (int off = 16; off; off >>= 1) {
                float ov = __shfl_xor_sync(0xffffffffu, bv, off);
                int   oi = __shfl_xor_sync(0xffffffffu, bi, off);
                int   os = __shfl_xor_sync(0xffffffffu, bs, off);
                if (ov > bv || (ov == bv && oi < bi)) { bv = ov; bi = oi; bs = os; }
            }
            if (d == 0) { sSel[it] = bs; sPr[it] = bv; }
            const int win = __shfl_sync(0xffffffffu, bs, 0);
            if (win == d)      va = -CUDART_INF_F;
            if (win == d + 32) vb = -CUDART_INF_F;
        }
        // softmax over selected values (sPr[0] is the max)
        float ev = (d < KT_) ? expf(sPr[d] - sPr[0]) : 0.f;
        float s = ev;
        #pragma unroll
        for (int off = 16; off; off >>= 1) s += __shfl_xor_sync(0xffffffffu, s, off);
        if (d < KT_) sPr[d] = ev / s;
    }
    __syncthreads();

    // gated message weights
    for (int k = w; k < KT_; k += 8) {
        const int s = sSel[k];
        const float pk = sPr[k], ck = 2.f - pk;
        float snb = 0.f, sg = 0.f;
        #pragma unroll
        for (int q = 0; q < 8; q++) {
            const int dd = lane + q * 32;
            const float nb = sNb[s][dd];
            snb += nb;
            sg  += tanhf(ck * sEh[dd] + pk * nb);
        }
        #pragma unroll
        for (int off = 16; off; off >>= 1) {
            snb += __shfl_xor_sync(0xffffffffu, snb, off);
            sg  += __shfl_xor_sync(0xffffffffu, sg,  off);
        }
        if (lane == 0) sW[k] = snb * sg;
    }
    __syncthreads();

    if (d < 32) {
        float val = (d < KT_) ? sW[d] : -CUDART_INF_F;
        float m = val;
        #pragma unroll
        for (int off = 16; off; off >>= 1) m = fmaxf(m, __shfl_xor_sync(0xffffffffu, m, off));
        float ev = (d < KT_) ? expf(val - m) : 0.f;
        float s = ev;
        #pragma unroll
        for (int off = 16; off; off >>= 1) s += __shfl_xor_sync(0xffffffffu, s, off);
        if (d < KT_) sKa[d] = ev / s;
    }
    __syncthreads();

    float acc = 0.f;
    #pragma unroll
    for (int k = 0; k < KT_; k++) acc += sKa[k] * sNb[sSel[k]][d];

    const float u = eh + acc, vv = eh * acc;
    {
        __nv_bfloat16 h = __float2bfloat16(u);
        __nv_bfloat16 l = __float2bfloat16(u - __bfloat162float(h));
        __nv_bfloat16* rw = Ub + (size_t)row * KA4_;
        rw[d] = h; rw[DD_ + d] = l; rw[2*DD_ + d] = h; rw[3*DD_ + d] = l;
    }
    {
        __nv_bfloat16 h = __float2bfloat16(vv);
        __nv_bfloat16 l = __float2bfloat16(vv - __bfloat162float(h));
        __nv_bfloat16* rw = Vb + (size_t)row * KA4_;
        rw[d] = h; rw[DD_ + d] = l; rw[2*DD_ + d] = h; rw[3*DD_ + d] = l;
    }
}

// ---------------- attention head ---------------------------------------------
__global__ void __launch_bounds__(128) att_kernel(
    const float* __restrict__ E, const float* __restrict__ W1,
    const float* __restrict__ b1, const float* __restrict__ W2,
    const float* __restrict__ b2, float* __restrict__ att)
{
    const int r0 = blockIdx.x * 16;
    const int j  = threadIdx.x;
    __shared__ float sE[16][DD_];
    for (int t = j; t < 16 * DD_; t += 128)
        sE[t >> 8][t & 255] = E[(size_t)(r0 + (t >> 8)) * DD_ + (t & 255)];
    __syncthreads();

    float acc[16];
    #pragma unroll
    for (int r = 0; r < 16; r++) acc[r] = 0.f;
    for (int dd = 0; dd < DD_; dd++) {
        const float wv = W1[dd * 128 + j];
        #pragma unroll
        for (int r = 0; r < 16; r++) acc[r] += sE[r][dd] * wv;
    }
    const float bb = b1[j], w2 = W2[j];
    __shared__ float sRed[16][4];
    const int lane = j & 31, w = j >> 5;
    #pragma unroll
    for (int r = 0; r < 16; r++) {
        float val = acc[r] + bb;
        val = (val > 0.f) ? val : 0.01f * val;
        val *= w2;
        #pragma unroll
        for (int off = 16; off; off >>= 1) val += __shfl_xor_sync(0xffffffffu, val, off);
        if (lane == 0) sRed[r][w] = val;
    }
    __syncthreads();
    if (j < 16) att[r0 + j] = sRed[j][0] + sRed[j][1] + sRed[j][2] + sRed[j][3] + b2[0];
}

// ---------------- softmax-over-nodes reduction -------------------------------
__global__ void __launch_bounds__(1024) smred_kernel(const float* __restrict__ att,
                                                     float* __restrict__ red)
{
    const int tid = threadIdx.x;
    __shared__ float s[32];
    float m = -CUDART_INF_F;
    for (int i = tid; i < NN_; i += 1024) m = fmaxf(m, att[i]);
    #pragma unroll
    for (int off = 16; off; off >>= 1) m = fmaxf(m, __shfl_xor_sync(0xffffffffu, m, off));
    if ((tid & 31) == 0) s[tid >> 5] = m;
    __syncthreads();
    if (tid < 32) {
        float mm = s[tid];
        #pragma unroll
        for (int off = 16; off; off >>= 1) mm = fmaxf(mm, __shfl_xor_sync(0xffffffffu, mm, off));
        if (tid == 0) s[0] = mm;
    }
    __syncthreads();
    const float M = s[0];
    __syncthreads();
    float z = 0.f;
    for (int i = tid; i < NN_; i += 1024) z += expf(att[i] - M);
    #pragma unroll
    for (int off = 16; off; off >>= 1) z += __shfl_xor_sync(0xffffffffu, z, off);
    if ((tid & 31) == 0) s[tid >> 5] = z;
    __syncthreads();
    if (tid < 32) {
        float zz = s[tid];
        #pragma unroll
        for (int off = 16; off; off >>= 1) zz += __shfl_xor_sync(0xffffffffu, zz, off);
        if (tid == 0) { red[0] = M; red[1] = zz; }
    }
}

__global__ void __launch_bounds__(256) egpart_kernel(const float* __restrict__ att,
    const float* __restrict__ E, const float* __restrict__ red, float* __restrict__ part)
{
    const int b = blockIdx.x;
    const int d = threadIdx.x;
    __shared__ float wsh[256];
    wsh[d] = expf(att[b * 256 + d] - red[0]);
    __syncthreads();
    float acc = 0.f;
    const float* Eb = E + (size_t)b * 256 * DD_;
    for (int i = 0; i < 256; i++) acc += wsh[i] * Eb[(size_t)i * DD_ + d];
    part[b * DD_ + d] = acc;
}

__global__ void __launch_bounds__(256) egfin_kernel(const float* __restrict__ part,
    const float* __restrict__ red, float* __restrict__ eg)
{
    const int d = threadIdx.x;
    float s = 0.f;
    #pragma unroll
    for (int b = 0; b < 32; b++) s += part[b * DD_ + d];
    eg[d] = s / red[1];
}

// ---------------- launcher ---------------------------------------------------
extern "C" void kernel_launch(void* const* d_in, const int* in_sizes, int n_in,
                              void* d_out, int out_size)
{
    const float* x    = (const float*)d_in[0];
    const float* Wfc1 = (const float*)d_in[1];
    const float* bfc1 = (const float*)d_in[2];
    const float* Wfc2 = (const float*)d_in[3];
    const float* bfc2 = (const float*)d_in[4];
    const float* Whd  = (const float*)d_in[5];
    const float* bhd  = (const float*)d_in[6];
    const float* Wtl  = (const float*)d_in[7];
    const float* btl  = (const float*)d_in[8];
    const float* Wl1  = (const float*)d_in[9];
    const float* bl1  = (const float*)d_in[10];
    const float* Wl2  = (const float*)d_in[11];
    const float* bl2  = (const float*)d_in[12];
    const float* Wa1  = (const float*)d_in[13];
    const float* ba1  = (const float*)d_in[14];
    const float* Wa2  = (const float*)d_in[15];
    const float* ba2  = (const float*)d_in[16];

    float *eh, *et, *E1, *spill, *att, *red, *part;
    __nv_bfloat16 *P, *Xbf, *h1b, *hb, *ehs, *ets, *Ub, *Vb;
    __nv_bfloat16 *Wfc1b, *Wfc2b, *Whdb, *Wtlb, *Wl1b, *Wl2b;
    int* tI;
    cudaGetSymbolAddress((void**)&P,     g_P);
    cudaGetSymbolAddress((void**)&eh,    g_eh);
    cudaGetSymbolAddress((void**)&et,    g_et);
    cudaGetSymbolAddress((void**)&E1,    g_E1);
    cudaGetSymbolAddress((void**)&spill, g_spill);
    cudaGetSymbolAddress((void**)&att,   g_att);
    cudaGetSymbolAddress((void**)&red,   g_red);
    cudaGetSymbolAddress((void**)&part,  g_part);
    cudaGetSymbolAddress((void**)&tI,    g_tI);
    cudaGetSymbolAddress((void**)&Xbf,   g_Xbf);
    cudaGetSymbolAddress((void**)&h1b,   g_h1b);
    cudaGetSymbolAddress((void**)&hb,    g_hb);
    cudaGetSymbolAddress((void**)&ehs,   g_ehs);
    cudaGetSymbolAddress((void**)&ets,   g_ets);
    cudaGetSymbolAddress((void**)&Ub,    g_Ub);
    cudaGetSymbolAddress((void**)&Vb,    g_Vb);
    cudaGetSymbolAddress((void**)&Wfc1b, g_Wfc1b);
    cudaGetSymbolAddress((void**)&Wfc2b, g_Wfc2b);
    cudaGetSymbolAddress((void**)&Whdb,  g_Whdb);
    cudaGetSymbolAddress((void**)&Wtlb,  g_Wtlb);
    cudaGetSymbolAddress((void**)&Wl1b,  g_Wl1b);
    cudaGetSymbolAddress((void**)&Wl2b,  g_Wl2b);

    cudaFuncSetAttribute(attn_mma_kernel,
                         cudaFuncAttributeMaxDynamicSharedMemorySize, 2 * MMA_STG);
    cudaFuncSetAttribute(mma_gemm_kernel<1, true,  false>,
                         cudaFuncAttributeMaxDynamicSharedMemorySize, 2 * MMA_STG);
    cudaFuncSetAttribute(mma_gemm_kernel<2, false, false>,
                         cudaFuncAttributeMaxDynamicSharedMemorySize, 2 * MMA_STG);
    cudaFuncSetAttribute(mma_gemm_kernel<3, false, false>,
                         cudaFuncAttributeMaxDynamicSharedMemorySize, 2 * MMA_STG);
    cudaFuncSetAttribute(mma_gemm_kernel<0, true,  false>,
                         cudaFuncAttributeMaxDynamicSharedMemorySize, 2 * MMA_STG);
    cudaFuncSetAttribute(mma_gemm_kernel<0, true,  true>,
                         cudaFuncAttributeMaxDynamicSharedMemorySize, 2 * MMA_STG);

    float* out = (float*)d_out;
    const size_t ND = (size_t)NN_ * DD_;
    float* e_out;
    float* eg_out;
    if ((size_t)out_size >= ND + DD_)      { e_out = out;   eg_out = out + ND; }
    else if ((size_t)out_size >= ND)       { e_out = out;   eg_out = nullptr;  }
    else                                   { e_out = spill; eg_out = out;      }

    const dim3 gG(2, 64);
    const dim3 gA(64, 64);

    // prep: input + weight splits
    xsplit_kernel<<<NN_, 256>>>(x, Xbf);
    wprep_kernel<<<DIN_, 256>>>(Wfc1, Wfc1b, DIN_);
    wprep_kernel<<<DD_,  256>>>(Wfc2, Wfc2b, DD_);
    wprep_kernel<<<DD_,  256>>>(Whd,  Whdb,  DD_);
    wprep_kernel<<<DD_,  256>>>(Wtl,  Wtlb,  DD_);
    wprep_kernel<<<DD_,  256>>>(Wl1,  Wl1b,  DD_);
    wprep_kernel<<<DD_,  256>>>(Wl2,  Wl2b,  DD_);

    // trunk on tensor cores (4-term split, fp32-accurate)
    mma_gemm_kernel<1, true,  false><<<gG, 256, 2*MMA_STG>>>(Xbf, Wfc1b, bfc1, nullptr, nullptr, h1b, KAX_, 0.f);
    mma_gemm_kernel<1, true,  false><<<gG, 256, 2*MMA_STG>>>(h1b, Wfc2b, bfc2, nullptr, nullptr, hb,  KA4_, 0.f);
    mma_gemm_kernel<2, false, false><<<gG, 256, 2*MMA_STG>>>(hb,  Whdb,  bhd,  nullptr, eh,      ehs, KA4_, 0.0625f);
    mma_gemm_kernel<3, false, false><<<gG, 256, 2*MMA_STG>>>(hb,  Wtlb,  btl,  nullptr, et,      ets, KA4_, 0.f);

    // screening logits (hi-only bf16, K=256) -> top-45 -> exact rescore+neighbor
    attn_mma_kernel<<<gA, 256, 2*MMA_STG>>>(ehs, ets, P);
    topk_kernel<<<NN_, 256>>>(P, tI);
    cand_kernel<<<NN_, 256>>>(eh, et, tI, Ub, Vb);

    // e = relu(U@Wl1+b) + relu(V@Wl2+b)
    mma_gemm_kernel<0, true, false><<<gG, 256, 2*MMA_STG>>>(Ub, Wl1b, bl1, nullptr, E1,    nullptr, KA4_, 0.f);
    mma_gemm_kernel<0, true, true ><<<gG, 256, 2*MMA_STG>>>(Vb, Wl2b, bl2, E1,      e_out, nullptr, KA4_, 0.f);

    if (eg_out) {
        att_kernel   <<<NN_ / 16, 128>>>(e_out, Wa1, ba1, Wa2, ba2, att);
        smred_kernel <<<1, 1024>>>(att, red);
        egpart_kernel<<<32, 256>>>(att, e_out, red, part);
        egfin_kernel <<<1, 256>>>(part, red, eg_out);
    }
}

// round 6
// speedup vs baseline: 1.1907x; 1.1907x over previous
#include <cuda_runtime.h>
#include <cuda_bf16.h>
#include <math_constants.h>
#include <cstdint>

#define NN_  8192
#define DIN_ 1024
#define DD_  256
#define KT_  30
#define KA3_ 768    // 3-term split row length (attn operands)
#define KA4_ 1024   // 4-term split row length (trunk operands)
#define KAX_ 4096   // 4-term split of x (K=1024)

// ---------------- scratch (static device globals: allocation-free) ----------
__device__ float g_P[(size_t)NN_ * NN_];     // attn logits fp32 (256 MB)
__device__ float g_eh[NN_ * DD_];
__device__ float g_et[NN_ * DD_];
__device__ float g_E1[NN_ * DD_];
__device__ float g_spill[NN_ * DD_];
__device__ __nv_bfloat16 g_Xbf [(size_t)NN_ * KAX_];
__device__ __nv_bfloat16 g_h1b [(size_t)NN_ * KA4_];
__device__ __nv_bfloat16 g_hb  [(size_t)NN_ * KA4_];
__device__ __nv_bfloat16 g_ehs [(size_t)NN_ * KA3_];
__device__ __nv_bfloat16 g_ets [(size_t)NN_ * KA3_];
__device__ __nv_bfloat16 g_Ub  [(size_t)NN_ * KA4_];
__device__ __nv_bfloat16 g_Vb  [(size_t)NN_ * KA4_];
__device__ __nv_bfloat16 g_Wfc1b[(size_t)DD_ * KAX_];
__device__ __nv_bfloat16 g_Wfc2b[DD_ * KA4_];
__device__ __nv_bfloat16 g_Whdb [DD_ * KA4_];
__device__ __nv_bfloat16 g_Wtlb [DD_ * KA4_];
__device__ __nv_bfloat16 g_Wl1b [DD_ * KA4_];
__device__ __nv_bfloat16 g_Wl2b [DD_ * KA4_];
__device__ int   g_tI[NN_ * KT_];
__device__ float g_tP[NN_ * KT_];
__device__ float g_att[NN_];
__device__ float g_red[2];
__device__ float g_part[32 * DD_];

// =================== warp-MMA helpers (sm_80+, compute_103-safe) ============
__device__ __forceinline__ uint32_t smem_u32(const void* p) {
    uint32_t a;
    asm("{ .reg .u64 t; cvta.to.shared.u64 t, %1; cvt.u32.u64 %0, t; }" : "=r"(a) : "l"(p));
    return a;
}
#define SW128(off) ((off) ^ (((off) >> 3) & 0x70))
#define CP16(dst, src)    asm volatile("cp.async.cg.shared.global [%0], [%1], 16;" :: "r"(dst), "l"(src) : "memory")
#define CP_COMMIT()       asm volatile("cp.async.commit_group;" ::: "memory")

__device__ __forceinline__ void ldsm4(uint32_t* r, uint32_t addr) {
    asm volatile("ldmatrix.sync.aligned.m8n8.x4.shared.b16 {%0,%1,%2,%3}, [%4];"
        : "=r"(r[0]), "=r"(r[1]), "=r"(r[2]), "=r"(r[3]) : "r"(addr));
}
__device__ __forceinline__ void mma16816(float* d, const uint32_t* a, const uint32_t* b) {
    asm volatile("mma.sync.aligned.m16n8k16.row.col.f32.bf16.bf16.f32 "
        "{%0,%1,%2,%3}, {%4,%5,%6,%7}, {%8,%9}, {%0,%1,%2,%3};"
        : "+f"(d[0]), "+f"(d[1]), "+f"(d[2]), "+f"(d[3])
        : "r"(a[0]), "r"(a[1]), "r"(a[2]), "r"(a[3]), "r"(b[0]), "r"(b[1]));
}

// ---------------- input / weight split prep ---------------------------------
__global__ void __launch_bounds__(256) xsplit_kernel(const float* __restrict__ x,
                                                     __nv_bfloat16* __restrict__ X)
{
    const int r = blockIdx.x;
    #pragma unroll
    for (int q = 0; q < 4; q++) {
        const int c = threadIdx.x + q * 256;
        float v = x[(size_t)r * DIN_ + c];
        __nv_bfloat16 h = __float2bfloat16(v);
        __nv_bfloat16 l = __float2bfloat16(v - __bfloat162float(h));
        __nv_bfloat16* row = X + (size_t)r * KAX_;
        row[c] = h; row[DIN_ + c] = l; row[2*DIN_ + c] = h; row[3*DIN_ + c] = l;
    }
}
// one kernel, all six weights: B4 layout [hi | hi | lo | lo], transposed
__global__ void __launch_bounds__(256) wprep6_kernel(
    const float* __restrict__ W1, const float* __restrict__ W2,
    const float* __restrict__ W3, const float* __restrict__ W4,
    const float* __restrict__ W5, const float* __restrict__ W6,
    __nv_bfloat16* __restrict__ B1, __nv_bfloat16* __restrict__ B2,
    __nv_bfloat16* __restrict__ B3, __nv_bfloat16* __restrict__ B4,
    __nv_bfloat16* __restrict__ B5, __nv_bfloat16* __restrict__ B6)
{
    int bid = blockIdx.x;
    const float* W; __nv_bfloat16* B; int K, k;
    if (bid < 1024)      { W = W1; B = B1; K = DIN_; k = bid; }
    else {
        bid -= 1024;
        const int s = bid >> 8;     // 0..4
        k = bid & 255; K = DD_;
        switch (s) {
            case 0: W = W2; B = B2; break;
            case 1: W = W3; B = B3; break;
            case 2: W = W4; B = B4; break;
            case 3: W = W5; B = B5; break;
            default: W = W6; B = B6; break;
        }
    }
    const int n = threadIdx.x;
    float v = W[(size_t)k * DD_ + n];
    __nv_bfloat16 h = __float2bfloat16(v);
    __nv_bfloat16 l = __float2bfloat16(v - __bfloat162float(h));
    __nv_bfloat16* row = B + (size_t)n * (4 * K);
    row[k] = h; row[K + k] = h; row[2*K + k] = l; row[3*K + k] = l;
}

// ---------------- shared tile fill (512 threads) ------------------------------
__device__ __forceinline__ void tile_fill(uint32_t sbase, int kc, int bm, int bn,
    const __nv_bfloat16* __restrict__ Ag, const __nv_bfloat16* __restrict__ Bg,
    int tid, int Ka)
{
    #pragma unroll
    for (int i = 0; i < 2; i++) {               // A: 128 rows x 128B
        int q = tid + i * 512;
        int row = q >> 3, c = q & 7;
        const __nv_bfloat16* src = Ag + (size_t)(bm * 128 + row) * Ka + kc * 64 + c * 8;
        CP16(sbase + SW128((uint32_t)(row * 128 + c * 16)), src);
    }
    #pragma unroll
    for (int i = 0; i < 2; i++) {               // B: 128 rows x 128B
        int q = tid + i * 512;
        int row = q >> 3, c = q & 7;
        const __nv_bfloat16* src = Bg + (size_t)(bn * 128 + row) * Ka + kc * 64 + c * 8;
        CP16(sbase + 16384 + SW128((uint32_t)(row * 128 + c * 16)), src);
    }
}

// ---------------- MMA mainloop (BM=BN=128, BK=64, 16 warps 4x4, wtile 32x32) -
#define MMA_STG 32768
struct MmaAcc { float a[2][4][4]; };   // 32 regs/thread

__device__ __forceinline__ void mma_mainloop(MmaAcc& A_, uint32_t sb, int nchunk,
    int bm, int bn, const __nv_bfloat16* Ag, const __nv_bfloat16* Bg, int Ka,
    int tid, int wid, int lane)
{
    const int wm = (wid & 3) * 32;
    const int wn = (wid >> 2) * 32;
    const int aRow = (lane & 15);
    const int aKb  = (lane >> 4) * 16;
    const int bRow = ((lane >> 4) << 3) + (lane & 7);
    const int bKb  = ((lane >> 3) & 1) * 16;

    tile_fill(sb, 0, bm, bn, Ag, Bg, tid, Ka);
    CP_COMMIT();

    for (int c = 0; c < nchunk; c++) {
        if (c + 1 < nchunk) {
            tile_fill(sb + ((c + 1) & 1) * MMA_STG, c + 1, bm, bn, Ag, Bg, tid, Ka);
            CP_COMMIT();
            asm volatile("cp.async.wait_group 1;" ::: "memory");
        } else {
            asm volatile("cp.async.wait_group 0;" ::: "memory");
        }
        __syncthreads();

        const uint32_t aB = sb + (c & 1) * MMA_STG;
        const uint32_t bB = aB + 16384;
        #pragma unroll
        for (int ks = 0; ks < 4; ks++) {
            uint32_t af[2][4];
            #pragma unroll
            for (int mt = 0; mt < 2; mt++) {
                int row = wm + mt * 16 + aRow;
                ldsm4(af[mt], aB + SW128((uint32_t)(row * 128 + ks * 32 + aKb)));
            }
            uint32_t bf[2][4];
            #pragma unroll
            for (int nt = 0; nt < 2; nt++) {
                int row = wn + nt * 16 + bRow;
                ldsm4(bf[nt], bB + SW128((uint32_t)(row * 128 + ks * 32 + bKb)));
            }
            #pragma unroll
            for (int mt = 0; mt < 2; mt++)
                #pragma unroll
                for (int n8 = 0; n8 < 4; n8++)
                    mma16816(A_.a[mt][n8], af[mt], &bf[n8 >> 1][(n8 & 1) * 2]);
        }
        __syncthreads();
    }
}

// ---------------- attn GEMM: P = ehs(A3) @ ets(B3)^T (fp32 out) --------------
__global__ void __launch_bounds__(512, 1) attn_mma_kernel(
    const __nv_bfloat16* __restrict__ Ag, const __nv_bfloat16* __restrict__ Bg,
    float* __restrict__ P)
{
    extern __shared__ char smem[];
    const uint32_t sb = smem_u32(smem);
    const int tid = threadIdx.x, wid = tid >> 5, lane = tid & 31;
    const int bn = blockIdx.x, bm = blockIdx.y;

    MmaAcc acc;
    #pragma unroll
    for (int i = 0; i < 2; i++)
        #pragma unroll
        for (int j = 0; j < 4; j++)
            #pragma unroll
            for (int q = 0; q < 4; q++) acc.a[i][j][q] = 0.f;

    mma_mainloop(acc, sb, KA3_ / 64, bm, bn, Ag, Bg, KA3_, tid, wid, lane);

    const int wm = (wid & 3) * 32, wn = (wid >> 2) * 32;
    const int tig = lane & 3, gid = lane >> 2;
    #pragma unroll
    for (int mt = 0; mt < 2; mt++) {
        const int r0 = bm * 128 + wm + mt * 16 + gid;
        #pragma unroll
        for (int n8 = 0; n8 < 4; n8++) {
            const int cc = bn * 128 + wn + n8 * 8 + tig * 2;
            *reinterpret_cast<float2*>(P + (size_t)r0 * NN_ + cc)
                = make_float2(acc.a[mt][n8][0], acc.a[mt][n8][1]);
            *reinterpret_cast<float2*>(P + (size_t)(r0 + 8) * NN_ + cc)
                = make_float2(acc.a[mt][n8][2], acc.a[mt][n8][3]);
        }
    }
}

// ---------------- trunk GEMM with fused split epilogues ---------------------
// OSPL: 0 none, 1 A4 [h|l|h|l], 2 A3-scaled [h|l|h], 3 B3 [h|h|l]
template<int OSPL, bool RELU, bool HASADD>
__global__ void __launch_bounds__(512, 1) mma_gemm_kernel(
    const __nv_bfloat16* __restrict__ Ag, const __nv_bfloat16* __restrict__ Bg,
    const float* __restrict__ bias, const float* __restrict__ addend,
    float* __restrict__ C, __nv_bfloat16* __restrict__ S, int Ka, float scale)
{
    extern __shared__ char smem[];
    const uint32_t sb = smem_u32(smem);
    const int tid = threadIdx.x, wid = tid >> 5, lane = tid & 31;
    const int bn = blockIdx.x, bm = blockIdx.y;

    MmaAcc acc;
    #pragma unroll
    for (int i = 0; i < 2; i++)
        #pragma unroll
        for (int j = 0; j < 4; j++)
            #pragma unroll
            for (int q = 0; q < 4; q++) acc.a[i][j][q] = 0.f;

    mma_mainloop(acc, sb, Ka / 64, bm, bn, Ag, Bg, Ka, tid, wid, lane);

    const int wm = (wid & 3) * 32, wn = (wid >> 2) * 32;
    const int tig = lane & 3, gid = lane >> 2;
    #pragma unroll
    for (int mt = 0; mt < 2; mt++) {
        #pragma unroll
        for (int n8 = 0; n8 < 4; n8++) {
            const int cc = bn * 128 + wn + n8 * 8 + tig * 2;
            #pragma unroll
            for (int hh = 0; hh < 2; hh++) {
                const int r = bm * 128 + wm + mt * 16 + gid + hh * 8;
                #pragma unroll
                for (int e = 0; e < 2; e++) {
                    const int c = cc + e;
                    float v = acc.a[mt][n8][hh * 2 + e] + bias[c];
                    if (RELU)   v = fmaxf(v, 0.f);
                    if (HASADD) v += addend[(size_t)r * DD_ + c];
                    if (C) C[(size_t)r * DD_ + c] = v;
                    if (OSPL == 1) {
                        __nv_bfloat16 h = __float2bfloat16(v);
                        __nv_bfloat16 l = __float2bfloat16(v - __bfloat162float(h));
                        __nv_bfloat16* row = S + (size_t)r * KA4_;
                        row[c] = h; row[DD_ + c] = l; row[2*DD_ + c] = h; row[3*DD_ + c] = l;
                    } else if (OSPL == 2) {
                        float vs = v * scale;
                        __nv_bfloat16 h = __float2bfloat16(vs);
                        __nv_bfloat16 l = __float2bfloat16(vs - __bfloat162float(h));
                        __nv_bfloat16* row = S + (size_t)r * KA3_;
                        row[c] = h; row[DD_ + c] = l; row[2*DD_ + c] = h;
                    } else if (OSPL == 3) {
                        __nv_bfloat16 h = __float2bfloat16(v);
                        __nv_bfloat16 l = __float2bfloat16(v - __bfloat162float(h));
                        __nv_bfloat16* row = S + (size_t)r * KA3_;
                        row[c] = h; row[DD_ + c] = h; row[2*DD_ + c] = l;
                    }
                }
            }
        }
    }
}

// ---------------- per-row top-30 (cached iterative argmax) -------------------
__global__ void __launch_bounds__(256) topk_kernel(const float* __restrict__ P,
                                                   int* __restrict__ tI,
                                                   float* __restrict__ tP)
{
    const int row  = blockIdx.x;
    const int tid  = threadIdx.x;
    const int lane = tid & 31, w = tid >> 5;
    const float* p = P + (size_t)row * NN_;

    float v[32];
    #pragma unroll
    for (int j = 0; j < 32; j++) v[j] = p[tid + j * 256];

    // cached per-thread argmax (strict > keeps lowest j => lowest global idx)
    float bv = v[0]; int bj = 0;
    #pragma unroll
    for (int j = 1; j < 32; j++) if (v[j] > bv) { bv = v[j]; bj = j; }

    __shared__ float sV[8];
    __shared__ int   sI[9];
    __shared__ float selV[KT_];
    __shared__ int   selI[KT_];

    for (int it = 0; it < KT_; it++) {
        float wv = bv; int wi = tid + bj * 256;
        #pragma unroll
        for (int off = 16; off; off >>= 1) {
            float ov = __shfl_xor_sync(0xffffffffu, wv, off);
            int   oi = __shfl_xor_sync(0xffffffffu, wi, off);
            if (ov > wv || (ov == wv && oi < wi)) { wv = ov; wi = oi; }
        }
        if (lane == 0) { sV[w] = wv; sI[w] = wi; }
        __syncthreads();
        if (tid == 0) {
            float Bv = sV[0]; int Bi = sI[0];
            #pragma unroll
            for (int q = 1; q < 8; q++)
                if (sV[q] > Bv || (sV[q] == Bv && sI[q] < Bi)) { Bv = sV[q]; Bi = sI[q]; }
            selV[it] = Bv; selI[it] = Bi; sI[8] = Bi;
        }
        __syncthreads();
        const int win = sI[8];
        if ((win & 255) == tid) {        // owner invalidates + refreshes cache
            v[win >> 8] = -CUDART_INF_F;
            bv = v[0]; bj = 0;
            #pragma unroll
            for (int j = 1; j < 32; j++) if (v[j] > bv) { bv = v[j]; bj = j; }
        }
    }
    __syncthreads();
    if (tid < 32) {
        float ev = (tid < KT_) ? expf(selV[tid] - selV[0]) : 0.f;
        float s = ev;
        #pragma unroll
        for (int off = 16; off; off >>= 1) s += __shfl_xor_sync(0xffffffffu, s, off);
        if (tid < KT_) {
            tP[row * KT_ + tid] = ev / s;
            tI[row * KT_ + tid] = selI[tid];
        }
    }
}

// ---------------- fused neighbor aggregation per row (R4 version) -----------
__global__ void __launch_bounds__(256) neighbor_kernel(
    const float* __restrict__ eH, const float* __restrict__ eT,
    const int* __restrict__ tI, const float* __restrict__ tP,
    __nv_bfloat16* __restrict__ Ub, __nv_bfloat16* __restrict__ Vb)
{
    const int row  = blockIdx.x;
    const int d    = threadIdx.x;
    const int lane = d & 31, w = d >> 5;

    __shared__ float sNb[KT_][DD_];
    __shared__ float sEh[DD_];
    __shared__ float sP[KT_];
    __shared__ int   sIdx[KT_];
    __shared__ float sW[KT_];
    __shared__ float sPr[KT_];

    const float eh = eH[(size_t)row * DD_ + d];
    sEh[d] = eh;
    if (d < KT_) { sP[d] = tP[row * KT_ + d]; sIdx[d] = tI[row * KT_ + d]; }
    __syncthreads();

    #pragma unroll
    for (int k = 0; k < KT_; k++) sNb[k][d] = eT[(size_t)sIdx[k] * DD_ + d];
    __syncthreads();

    for (int k = w; k < KT_; k += 8) {
        const float pk = sP[k], ck = 2.f - pk;
        float snb = 0.f, sg = 0.f;
        #pragma unroll
        for (int q = 0; q < 8; q++) {
            const int dd = lane + q * 32;
            const float nb = sNb[k][dd];
            snb += nb;
            sg  += tanhf(ck * sEh[dd] + pk * nb);
        }
        #pragma unroll
        for (int off = 16; off; off >>= 1) {
            snb += __shfl_xor_sync(0xffffffffu, snb, off);
            sg  += __shfl_xor_sync(0xffffffffu, sg,  off);
        }
        if (lane == 0) sW[k] = snb * sg;
    }
    __syncthreads();

    if (d < 32) {
        float val = (d < KT_) ? sW[d] : -CUDART_INF_F;
        float m = val;
        #pragma unroll
        for (int off = 16; off; off >>= 1) m = fmaxf(m, __shfl_xor_sync(0xffffffffu, m, off));
        float ev = (d < KT_) ? expf(val - m) : 0.f;
        float s = ev;
        #pragma unroll
        for (int off = 16; off; off >>= 1) s += __shfl_xor_sync(0xffffffffu, s, off);
        if (d < KT_) sPr[d] = ev / s;
    }
    __syncthreads();

    float acc = 0.f;
    #pragma unroll
    for (int k = 0; k < KT_; k++) acc += sPr[k] * sNb[k][d];

    const float u = eh + acc, vv = eh * acc;
    {
        __nv_bfloat16 h = __float2bfloat16(u);
        __nv_bfloat16 l = __float2bfloat16(u - __bfloat162float(h));
        __nv_bfloat16* rw = Ub + (size_t)row * KA4_;
        rw[d] = h; rw[DD_ + d] = l; rw[2*DD_ + d] = h; rw[3*DD_ + d] = l;
    }
    {
        __nv_bfloat16 h = __float2bfloat16(vv);
        __nv_bfloat16 l = __float2bfloat16(vv - __bfloat162float(h));
        __nv_bfloat16* rw = Vb + (size_t)row * KA4_;
        rw[d] = h; rw[DD_ + d] = l; rw[2*DD_ + d] = h; rw[3*DD_ + d] = l;
    }
}

// ---------------- attention head ---------------------------------------------
__global__ void __launch_bounds__(128) att_kernel(
    const float* __restrict__ E, const float* __restrict__ W1,
    const float* __restrict__ b1, const float* __restrict__ W2,
    const float* __restrict__ b2, float* __restrict__ att)
{
    const int r0 = blockIdx.x * 16;
    const int j  = threadIdx.x;
    __shared__ float sE[16][DD_];
    for (int t = j; t < 16 * DD_; t += 128)
        sE[t >> 8][t & 255] = E[(size_t)(r0 + (t >> 8)) * DD_ + (t & 255)];
    __syncthreads();

    float acc[16];
    #pragma unroll
    for (int r = 0; r < 16; r++) acc[r] = 0.f;
    for (int dd = 0; dd < DD_; dd++) {
        const float wv = W1[dd * 128 + j];
        #pragma unroll
        for (int r = 0; r < 16; r++) acc[r] += sE[r][dd] * wv;
    }
    const float bb = b1[j], w2 = W2[j];
    __shared__ float sRed[16][4];
    const int lane = j & 31, w = j >> 5;
    #pragma unroll
    for (int r = 0; r < 16; r++) {
        float val = acc[r] + bb;
        val = (val > 0.f) ? val : 0.01f * val;
        val *= w2;
        #pragma unroll
        for (int off = 16; off; off >>= 1) val += __shfl_xor_sync(0xffffffffu, val, off);
        if (lane == 0) sRed[r][w] = val;
    }
    __syncthreads();
    if (j < 16) att[r0 + j] = sRed[j][0] + sRed[j][1] + sRed[j][2] + sRed[j][3] + b2[0];
}

// ---------------- softmax-over-nodes reduction -------------------------------
__global__ void __launch_bounds__(1024) smred_kernel(const float* __restrict__ att,
                                                     float* __restrict__ red)
{
    const int tid = threadIdx.x;
    __shared__ float s[32];
    float m = -CUDART_INF_F;
    for (int i = tid; i < NN_; i += 1024) m = fmaxf(m, att[i]);
    #pragma unroll
    for (int off = 16; off; off >>= 1) m = fmaxf(m, __shfl_xor_sync(0xffffffffu, m, off));
    if ((tid & 31) == 0) s[tid >> 5] = m;
    __syncthreads();
    if (tid < 32) {
        float mm = s[tid];
        #pragma unroll
        for (int off = 16; off; off >>= 1) mm = fmaxf(mm, __shfl_xor_sync(0xffffffffu, mm, off));
        if (tid == 0) s[0] = mm;
    }
    __syncthreads();
    const float M = s[0];
    __syncthreads();
    float z = 0.f;
    for (int i = tid; i < NN_; i += 1024) z += expf(att[i] - M);
    #pragma unroll
    for (int off = 16; off; off >>= 1) z += __shfl_xor_sync(0xffffffffu, z, off);
    if ((tid & 31) == 0) s[tid >> 5] = z;
    __syncthreads();
    if (tid < 32) {
        float zz = s[tid];
        #pragma unroll
        for (int off = 16; off; off >>= 1) zz += __shfl_xor_sync(0xffffffffu, zz, off);
        if (tid == 0) { red[0] = M; red[1] = zz; }
    }
}

__global__ void __launch_bounds__(256) egpart_kernel(const float* __restrict__ att,
    const float* __restrict__ E, const float* __restrict__ red, float* __restrict__ part)
{
    const int b = blockIdx.x;
    const int d = threadIdx.x;
    __shared__ float wsh[256];
    wsh[d] = expf(att[b * 256 + d] - red[0]);
    __syncthreads();
    float acc = 0.f;
    const float* Eb = E + (size_t)b * 256 * DD_;
    for (int i = 0; i < 256; i++) acc += wsh[i] * Eb[(size_t)i * DD_ + d];
    part[b * DD_ + d] = acc;
}

__global__ void __launch_bounds__(256) egfin_kernel(const float* __restrict__ part,
    const float* __restrict__ red, float* __restrict__ eg)
{
    const int d = threadIdx.x;
    float s = 0.f;
    #pragma unroll
    for (int b = 0; b < 32; b++) s += part[b * DD_ + d];
    eg[d] = s / red[1];
}

// ---------------- launcher ---------------------------------------------------
extern "C" void kernel_launch(void* const* d_in, const int* in_sizes, int n_in,
                              void* d_out, int out_size)
{
    const float* x    = (const float*)d_in[0];
    const float* Wfc1 = (const float*)d_in[1];
    const float* bfc1 = (const float*)d_in[2];
    const float* Wfc2 = (const float*)d_in[3];
    const float* bfc2 = (const float*)d_in[4];
    const float* Whd  = (const float*)d_in[5];
    const float* bhd  = (const float*)d_in[6];
    const float* Wtl  = (const float*)d_in[7];
    const float* btl  = (const float*)d_in[8];
    const float* Wl1  = (const float*)d_in[9];
    const float* bl1  = (const float*)d_in[10];
    const float* Wl2  = (const float*)d_in[11];
    const float* bl2  = (const float*)d_in[12];
    const float* Wa1  = (const float*)d_in[13];
    const float* ba1  = (const float*)d_in[14];
    const float* Wa2  = (const float*)d_in[15];
    const float* ba2  = (const float*)d_in[16];

    float *P, *eh, *et, *E1, *spill, *att, *red, *part, *tP;
    __nv_bfloat16 *Xbf, *h1b, *hb, *ehs, *ets, *Ub, *Vb;
    __nv_bfloat16 *Wfc1b, *Wfc2b, *Whdb, *Wtlb, *Wl1b, *Wl2b;
    int* tI;
    cudaGetSymbolAddress((void**)&P,     g_P);
    cudaGetSymbolAddress((void**)&eh,    g_eh);
    cudaGetSymbolAddress((void**)&et,    g_et);
    cudaGetSymbolAddress((void**)&E1,    g_E1);
    cudaGetSymbolAddress((void**)&spill, g_spill);
    cudaGetSymbolAddress((void**)&att,   g_att);
    cudaGetSymbolAddress((void**)&red,   g_red);
    cudaGetSymbolAddress((void**)&part,  g_part);
    cudaGetSymbolAddress((void**)&tI,    g_tI);
    cudaGetSymbolAddress((void**)&tP,    g_tP);
    cudaGetSymbolAddress((void**)&Xbf,   g_Xbf);
    cudaGetSymbolAddress((void**)&h1b,   g_h1b);
    cudaGetSymbolAddress((void**)&hb,    g_hb);
    cudaGetSymbolAddress((void**)&ehs,   g_ehs);
    cudaGetSymbolAddress((void**)&ets,   g_ets);
    cudaGetSymbolAddress((void**)&Ub,    g_Ub);
    cudaGetSymbolAddress((void**)&Vb,    g_Vb);
    cudaGetSymbolAddress((void**)&Wfc1b, g_Wfc1b);
    cudaGetSymbolAddress((void**)&Wfc2b, g_Wfc2b);
    cudaGetSymbolAddress((void**)&Whdb,  g_Whdb);
    cudaGetSymbolAddress((void**)&Wtlb,  g_Wtlb);
    cudaGetSymbolAddress((void**)&Wl1b,  g_Wl1b);
    cudaGetSymbolAddress((void**)&Wl2b,  g_Wl2b);

    cudaFuncSetAttribute(attn_mma_kernel,
                         cudaFuncAttributeMaxDynamicSharedMemorySize, 2 * MMA_STG);
    cudaFuncSetAttribute(mma_gemm_kernel<1, true,  false>,
                         cudaFuncAttributeMaxDynamicSharedMemorySize, 2 * MMA_STG);
    cudaFuncSetAttribute(mma_gemm_kernel<2, false, false>,
                         cudaFuncAttributeMaxDynamicSharedMemorySize, 2 * MMA_STG);
    cudaFuncSetAttribute(mma_gemm_kernel<3, false, false>,
                         cudaFuncAttributeMaxDynamicSharedMemorySize, 2 * MMA_STG);
    cudaFuncSetAttribute(mma_gemm_kernel<0, true,  false>,
                         cudaFuncAttributeMaxDynamicSharedMemorySize, 2 * MMA_STG);
    cudaFuncSetAttribute(mma_gemm_kernel<0, true,  true>,
                         cudaFuncAttributeMaxDynamicSharedMemorySize, 2 * MMA_STG);

    float* out = (float*)d_out;
    const size_t ND = (size_t)NN_ * DD_;
    float* e_out;
    float* eg_out;
    if ((size_t)out_size >= ND + DD_)      { e_out = out;   eg_out = out + ND; }
    else if ((size_t)out_size >= ND)       { e_out = out;   eg_out = nullptr;  }
    else                                   { e_out = spill; eg_out = out;      }

    const dim3 gG(2, 64);
    const dim3 gA(64, 64);

    // prep: input + all weight splits
    xsplit_kernel<<<NN_, 256>>>(x, Xbf);
    wprep6_kernel<<<DIN_ + 5 * DD_, 256>>>(Wfc1, Wfc2, Whd, Wtl, Wl1, Wl2,
                                           Wfc1b, Wfc2b, Whdb, Wtlb, Wl1b, Wl2b);

    // trunk on tensor cores (4-term split, fp32-accurate)
    mma_gemm_kernel<1, true,  false><<<gG, 512, 2*MMA_STG>>>(Xbf, Wfc1b, bfc1, nullptr, nullptr, h1b, KAX_, 0.f);
    mma_gemm_kernel<1, true,  false><<<gG, 512, 2*MMA_STG>>>(h1b, Wfc2b, bfc2, nullptr, nullptr, hb,  KA4_, 0.f);
    mma_gemm_kernel<2, false, false><<<gG, 512, 2*MMA_STG>>>(hb,  Whdb,  bhd,  nullptr, eh,      ehs, KA4_, 0.0625f);
    mma_gemm_kernel<3, false, false><<<gG, 512, 2*MMA_STG>>>(hb,  Wtlb,  btl,  nullptr, et,      ets, KA4_, 0.f);

    // pairwise logits (3-term split) + top-k + neighbor aggregation
    attn_mma_kernel<<<gA, 512, 2*MMA_STG>>>(ehs, ets, P);
    topk_kernel    <<<NN_, 256>>>(P, tI, tP);
    neighbor_kernel<<<NN_, 256>>>(eh, et, tI, tP, Ub, Vb);

    // e = relu(U@Wl1+b) + relu(V@Wl2+b)
    mma_gemm_kernel<0, true, false><<<gG, 512, 2*MMA_STG>>>(Ub, Wl1b, bl1, nullptr, E1,    nullptr, KA4_, 0.f);
    mma_gemm_kernel<0, true, true ><<<gG, 512, 2*MMA_STG>>>(Vb, Wl2b, bl2, E1,      e_out, nullptr, KA4_, 0.f);

    if (eg_out) {
        att_kernel   <<<NN_ / 16, 128>>>(e_out, Wa1, ba1, Wa2, ba2, att);
        smred_kernel <<<1, 1024>>>(att, red);
        egpart_kernel<<<32, 256>>>(att, e_out, red, part);
        egfin_kernel <<<1, 256>>>(part, red, eg_out);
    }
}

// round 7
// speedup vs baseline: 1.2644x; 1.0620x over previous
#include <cuda_runtime.h>
#include <cuda_bf16.h>
#include <math_constants.h>
#include <cstdint>

#define NN_  8192
#define DIN_ 1024
#define DD_  256
#define KT_  30
#define KA3_ 768    // 3-term split row length (attn operands)
#define KA4_ 1024   // 4-term split row length (trunk operands)
#define KAX_ 4096   // 4-term split of x (K=1024)

// ---------------- scratch (static device globals: allocation-free) ----------
__device__ float g_P[(size_t)NN_ * NN_];     // attn logits fp32 (256 MB)
__device__ float g_eh[NN_ * DD_];
__device__ float g_et[NN_ * DD_];
__device__ float g_E1[NN_ * DD_];
__device__ float g_spill[NN_ * DD_];
__device__ __nv_bfloat16 g_Xbf [(size_t)NN_ * KAX_];
__device__ __nv_bfloat16 g_h1b [(size_t)NN_ * KA4_];
__device__ __nv_bfloat16 g_hb  [(size_t)NN_ * KA4_];
__device__ __nv_bfloat16 g_ehs [(size_t)NN_ * KA3_];
__device__ __nv_bfloat16 g_ets [(size_t)NN_ * KA3_];
__device__ __nv_bfloat16 g_Ub  [(size_t)NN_ * KA4_];
__device__ __nv_bfloat16 g_Vb  [(size_t)NN_ * KA4_];
__device__ __nv_bfloat16 g_Wfc1b[(size_t)DD_ * KAX_];
__device__ __nv_bfloat16 g_Wfc2b[DD_ * KA4_];
__device__ __nv_bfloat16 g_Whdb [DD_ * KA4_];
__device__ __nv_bfloat16 g_Wtlb [DD_ * KA4_];
__device__ __nv_bfloat16 g_Wl1b [DD_ * KA4_];
__device__ __nv_bfloat16 g_Wl2b [DD_ * KA4_];
__device__ int   g_tI[NN_ * KT_];
__device__ float g_tP[NN_ * KT_];
__device__ float g_att[NN_];
__device__ float g_red[2];
__device__ float g_part[32 * DD_];

// =================== warp-MMA helpers (sm_80+, compute_103-safe) ============
__device__ __forceinline__ uint32_t smem_u32(const void* p) {
    uint32_t a;
    asm("{ .reg .u64 t; cvta.to.shared.u64 t, %1; cvt.u32.u64 %0, t; }" : "=r"(a) : "l"(p));
    return a;
}
#define SW128(off) ((off) ^ (((off) >> 3) & 0x70))
#define CP16(dst, src)    asm volatile("cp.async.cg.shared.global [%0], [%1], 16;" :: "r"(dst), "l"(src) : "memory")
#define CP_COMMIT()       asm volatile("cp.async.commit_group;" ::: "memory")

__device__ __forceinline__ void ldsm4(uint32_t* r, uint32_t addr) {
    asm volatile("ldmatrix.sync.aligned.m8n8.x4.shared.b16 {%0,%1,%2,%3}, [%4];"
        : "=r"(r[0]), "=r"(r[1]), "=r"(r[2]), "=r"(r[3]) : "r"(addr));
}
__device__ __forceinline__ void mma16816(float* d, const uint32_t* a, const uint32_t* b) {
    asm volatile("mma.sync.aligned.m16n8k16.row.col.f32.bf16.bf16.f32 "
        "{%0,%1,%2,%3}, {%4,%5,%6,%7}, {%8,%9}, {%0,%1,%2,%3};"
        : "+f"(d[0]), "+f"(d[1]), "+f"(d[2]), "+f"(d[3])
        : "r"(a[0]), "r"(a[1]), "r"(a[2]), "r"(a[3]), "r"(b[0]), "r"(b[1]));
}

// ---------------- input / weight split prep ---------------------------------
__global__ void __launch_bounds__(256) xsplit_kernel(const float* __restrict__ x,
                                                     __nv_bfloat16* __restrict__ X)
{
    const int r = blockIdx.x;
    #pragma unroll
    for (int q = 0; q < 4; q++) {
        const int c = threadIdx.x + q * 256;
        float v = x[(size_t)r * DIN_ + c];
        __nv_bfloat16 h = __float2bfloat16(v);
        __nv_bfloat16 l = __float2bfloat16(v - __bfloat162float(h));
        __nv_bfloat16* row = X + (size_t)r * KAX_;
        row[c] = h; row[DIN_ + c] = l; row[2*DIN_ + c] = h; row[3*DIN_ + c] = l;
    }
}
__global__ void __launch_bounds__(256) wprep6_kernel(
    const float* __restrict__ W1, const float* __restrict__ W2,
    const float* __restrict__ W3, const float* __restrict__ W4,
    const float* __restrict__ W5, const float* __restrict__ W6,
    __nv_bfloat16* __restrict__ B1, __nv_bfloat16* __restrict__ B2,
    __nv_bfloat16* __restrict__ B3, __nv_bfloat16* __restrict__ B4,
    __nv_bfloat16* __restrict__ B5, __nv_bfloat16* __restrict__ B6)
{
    int bid = blockIdx.x;
    const float* W; __nv_bfloat16* B; int K, k;
    if (bid < 1024)      { W = W1; B = B1; K = DIN_; k = bid; }
    else {
        bid -= 1024;
        const int s = bid >> 8;
        k = bid & 255; K = DD_;
        switch (s) {
            case 0: W = W2; B = B2; break;
            case 1: W = W3; B = B3; break;
            case 2: W = W4; B = B4; break;
            case 3: W = W5; B = B5; break;
            default: W = W6; B = B6; break;
        }
    }
    const int n = threadIdx.x;
    float v = W[(size_t)k * DD_ + n];
    __nv_bfloat16 h = __float2bfloat16(v);
    __nv_bfloat16 l = __float2bfloat16(v - __bfloat162float(h));
    __nv_bfloat16* row = B + (size_t)n * (4 * K);
    row[k] = h; row[K + k] = h; row[2*K + k] = l; row[3*K + k] = l;
}

// ---------------- shared tile fill (512 threads) ------------------------------
__device__ __forceinline__ void tile_fill(uint32_t sbase, int kc, int bm, int bn,
    const __nv_bfloat16* __restrict__ Ag, const __nv_bfloat16* __restrict__ Bg,
    int tid, int Ka)
{
    #pragma unroll
    for (int i = 0; i < 2; i++) {               // A: 128 rows x 128B
        int q = tid + i * 512;
        int row = q >> 3, c = q & 7;
        const __nv_bfloat16* src = Ag + (size_t)(bm * 128 + row) * Ka + kc * 64 + c * 8;
        CP16(sbase + SW128((uint32_t)(row * 128 + c * 16)), src);
    }
    #pragma unroll
    for (int i = 0; i < 2; i++) {               // B: 128 rows x 128B
        int q = tid + i * 512;
        int row = q >> 3, c = q & 7;
        const __nv_bfloat16* src = Bg + (size_t)(bn * 128 + row) * Ka + kc * 64 + c * 8;
        CP16(sbase + 16384 + SW128((uint32_t)(row * 128 + c * 16)), src);
    }
}

// ---- MMA mainloop: BM=BN=128, BK=64, 16 warps 4x4, 3-stage, 1 barrier/chunk -
#define MMA_STG 32768
struct MmaAcc { float a[2][4][4]; };   // 32 regs/thread

__device__ __forceinline__ void mma_mainloop(MmaAcc& A_, uint32_t sb, int nchunk,
    int bm, int bn, const __nv_bfloat16* Ag, const __nv_bfloat16* Bg, int Ka,
    int tid, int wid, int lane)
{
    const int wm = (wid & 3) * 32;
    const int wn = (wid >> 2) * 32;
    const int aRow = (lane & 15);
    const int aKb  = (lane >> 4) * 16;
    const int bRow = ((lane >> 4) << 3) + (lane & 7);
    const int bKb  = ((lane >> 3) & 1) * 16;

    // precomputed swizzled ks=0 offsets; per-ks address = base ^ (ks<<5)
    // (valid: ks*32 only toggles bits 5-6, carry-free, swizzle bits from row only)
    uint32_t aOff[2], bOff[2];
    aOff[0] = SW128((uint32_t)((wm +      aRow) * 128 + aKb));
    aOff[1] = SW128((uint32_t)((wm + 16 + aRow) * 128 + aKb));
    bOff[0] = SW128((uint32_t)((wn +      bRow) * 128 + bKb)) + 16384u;
    bOff[1] = SW128((uint32_t)((wn + 16 + bRow) * 128 + bKb)) + 16384u;

    // prologue: fill stages 0 and 1
    tile_fill(sb,            0, bm, bn, Ag, Bg, tid, Ka);
    CP_COMMIT();
    tile_fill(sb + MMA_STG,  1, bm, bn, Ag, Bg, tid, Ka);
    CP_COMMIT();

    int sidx = 0;
    for (int c = 0; c < nchunk; c++) {
        asm volatile("cp.async.wait_group 1;" ::: "memory");
        __syncthreads();   // all warps past compute(c-1); fill(c) landed

        if (c + 2 < nchunk) {
            int s2 = sidx + 2; if (s2 >= 3) s2 -= 3;
            tile_fill(sb + s2 * MMA_STG, c + 2, bm, bn, Ag, Bg, tid, Ka);
            CP_COMMIT();
        }

        const uint32_t stg = sb + sidx * MMA_STG;
        uint32_t abuf[2][2][4], bbuf[2][2][4];
        ldsm4(abuf[0][0], stg + aOff[0]);
        ldsm4(abuf[0][1], stg + aOff[1]);
        ldsm4(bbuf[0][0], stg + bOff[0]);
        ldsm4(bbuf[0][1], stg + bOff[1]);
        #pragma unroll
        for (int ks = 0; ks < 4; ks++) {
            const int cur = ks & 1, nxt = cur ^ 1;
            if (ks < 3) {
                const uint32_t x = (uint32_t)(ks + 1) << 5;
                ldsm4(abuf[nxt][0], (stg + aOff[0]) ^ x);
                ldsm4(abuf[nxt][1], (stg + aOff[1]) ^ x);
                ldsm4(bbuf[nxt][0], (stg + bOff[0]) ^ x);
                ldsm4(bbuf[nxt][1], (stg + bOff[1]) ^ x);
            }
            #pragma unroll
            for (int mt = 0; mt < 2; mt++)
                #pragma unroll
                for (int n8 = 0; n8 < 4; n8++)
                    mma16816(A_.a[mt][n8], abuf[cur][mt], &bbuf[cur][n8 >> 1][(n8 & 1) * 2]);
        }
        if (++sidx == 3) sidx = 0;
    }
}

// ---------------- attn GEMM: P = ehs(A3) @ ets(B3)^T (fp32 out) --------------
__global__ void __launch_bounds__(512, 1) attn_mma_kernel(
    const __nv_bfloat16* __restrict__ Ag, const __nv_bfloat16* __restrict__ Bg,
    float* __restrict__ P)
{
    extern __shared__ char smem[];
    const uint32_t sb = smem_u32(smem);
    const int tid = threadIdx.x, wid = tid >> 5, lane = tid & 31;
    const int bn = blockIdx.x, bm = blockIdx.y;

    MmaAcc acc;
    #pragma unroll
    for (int i = 0; i < 2; i++)
        #pragma unroll
        for (int j = 0; j < 4; j++)
            #pragma unroll
            for (int q = 0; q < 4; q++) acc.a[i][j][q] = 0.f;

    mma_mainloop(acc, sb, KA3_ / 64, bm, bn, Ag, Bg, KA3_, tid, wid, lane);

    const int wm = (wid & 3) * 32, wn = (wid >> 2) * 32;
    const int tig = lane & 3, gid = lane >> 2;
    #pragma unroll
    for (int mt = 0; mt < 2; mt++) {
        const int r0 = bm * 128 + wm + mt * 16 + gid;
        #pragma unroll
        for (int n8 = 0; n8 < 4; n8++) {
            const int cc = bn * 128 + wn + n8 * 8 + tig * 2;
            *reinterpret_cast<float2*>(P + (size_t)r0 * NN_ + cc)
                = make_float2(acc.a[mt][n8][0], acc.a[mt][n8][1]);
            *reinterpret_cast<float2*>(P + (size_t)(r0 + 8) * NN_ + cc)
                = make_float2(acc.a[mt][n8][2], acc.a[mt][n8][3]);
        }
    }
}

// ---------------- trunk GEMM with fused split epilogues ---------------------
// OSPL: 0 none, 1 A4 [h|l|h|l], 2 A3-scaled [h|l|h], 3 B3 [h|h|l]
template<int OSPL, bool RELU, bool HASADD>
__global__ void __launch_bounds__(512, 1) mma_gemm_kernel(
    const __nv_bfloat16* __restrict__ Ag, const __nv_bfloat16* __restrict__ Bg,
    const float* __restrict__ bias, const float* __restrict__ addend,
    float* __restrict__ C, __nv_bfloat16* __restrict__ S, int Ka, float scale)
{
    extern __shared__ char smem[];
    const uint32_t sb = smem_u32(smem);
    const int tid = threadIdx.x, wid = tid >> 5, lane = tid & 31;
    const int bn = blockIdx.x, bm = blockIdx.y;

    MmaAcc acc;
    #pragma unroll
    for (int i = 0; i < 2; i++)
        #pragma unroll
        for (int j = 0; j < 4; j++)
            #pragma unroll
            for (int q = 0; q < 4; q++) acc.a[i][j][q] = 0.f;

    mma_mainloop(acc, sb, Ka / 64, bm, bn, Ag, Bg, Ka, tid, wid, lane);

    const int wm = (wid & 3) * 32, wn = (wid >> 2) * 32;
    const int tig = lane & 3, gid = lane >> 2;
    #pragma unroll
    for (int mt = 0; mt < 2; mt++) {
        #pragma unroll
        for (int n8 = 0; n8 < 4; n8++) {
            const int cc = bn * 128 + wn + n8 * 8 + tig * 2;
            #pragma unroll
            for (int hh = 0; hh < 2; hh++) {
                const int r = bm * 128 + wm + mt * 16 + gid + hh * 8;
                #pragma unroll
                for (int e = 0; e < 2; e++) {
                    const int c = cc + e;
                    float v = acc.a[mt][n8][hh * 2 + e] + bias[c];
                    if (RELU)   v = fmaxf(v, 0.f);
                    if (HASADD) v += addend[(size_t)r * DD_ + c];
                    if (C) C[(size_t)r * DD_ + c] = v;
                    if (OSPL == 1) {
                        __nv_bfloat16 h = __float2bfloat16(v);
                        __nv_bfloat16 l = __float2bfloat16(v - __bfloat162float(h));
                        __nv_bfloat16* row = S + (size_t)r * KA4_;
                        row[c] = h; row[DD_ + c] = l; row[2*DD_ + c] = h; row[3*DD_ + c] = l;
                    } else if (OSPL == 2) {
                        float vs = v * scale;
                        __nv_bfloat16 h = __float2bfloat16(vs);
                        __nv_bfloat16 l = __float2bfloat16(vs - __bfloat162float(h));
                        __nv_bfloat16* row = S + (size_t)r * KA3_;
                        row[c] = h; row[DD_ + c] = l; row[2*DD_ + c] = h;
                    } else if (OSPL == 3) {
                        __nv_bfloat16 h = __float2bfloat16(v);
                        __nv_bfloat16 l = __float2bfloat16(v - __bfloat162float(h));
                        __nv_bfloat16* row = S + (size_t)r * KA3_;
                        row[c] = h; row[DD_ + c] = h; row[2*DD_ + c] = l;
                    }
                }
            }
        }
    }
}

// ---------------- per-row top-30 (cached iterative argmax) -------------------
__global__ void __launch_bounds__(256) topk_kernel(const float* __restrict__ P,
                                                   int* __restrict__ tI,
                                                   float* __restrict__ tP)
{
    const int row  = blockIdx.x;
    const int tid  = threadIdx.x;
    const int lane = tid & 31, w = tid >> 5;
    const float* p = P + (size_t)row * NN_;

    float v[32];
    #pragma unroll
    for (int j = 0; j < 32; j++) v[j] = p[tid + j * 256];

    float bv = v[0]; int bj = 0;
    #pragma unroll
    for (int j = 1; j < 32; j++) if (v[j] > bv) { bv = v[j]; bj = j; }

    __shared__ float sV[8];
    __shared__ int   sI[9];
    __shared__ float selV[KT_];
    __shared__ int   selI[KT_];

    for (int it = 0; it < KT_; it++) {
        float wv = bv; int wi = tid + bj * 256;
        #pragma unroll
        for (int off = 16; off; off >>= 1) {
            float ov = __shfl_xor_sync(0xffffffffu, wv, off);
            int   oi = __shfl_xor_sync(0xffffffffu, wi, off);
            if (ov > wv || (ov == wv && oi < wi)) { wv = ov; wi = oi; }
        }
        if (lane == 0) { sV[w] = wv; sI[w] = wi; }
        __syncthreads();
        if (tid == 0) {
            float Bv = sV[0]; int Bi = sI[0];
            #pragma unroll
            for (int q = 1; q < 8; q++)
                if (sV[q] > Bv || (sV[q] == Bv && sI[q] < Bi)) { Bv = sV[q]; Bi = sI[q]; }
            selV[it] = Bv; selI[it] = Bi; sI[8] = Bi;
        }
        __syncthreads();
        const int win = sI[8];
        if ((win & 255) == tid) {
            v[win >> 8] = -CUDART_INF_F;
            bv = v[0]; bj = 0;
            #pragma unroll
            for (int j = 1; j < 32; j++) if (v[j] > bv) { bv = v[j]; bj = j; }
        }
    }
    __syncthreads();
    if (tid < 32) {
        float ev = (tid < KT_) ? expf(selV[tid] - selV[0]) : 0.f;
        float s = ev;
        #pragma unroll
        for (int off = 16; off; off >>= 1) s += __shfl_xor_sync(0xffffffffu, s, off);
        if (tid < KT_) {
            tP[row * KT_ + tid] = ev / s;
            tI[row * KT_ + tid] = selI[tid];
        }
    }
}

// ---------------- fused neighbor aggregation per row -------------------------
__global__ void __launch_bounds__(256) neighbor_kernel(
    const float* __restrict__ eH, const float* __restrict__ eT,
    const int* __restrict__ tI, const float* __restrict__ tP,
    __nv_bfloat16* __restrict__ Ub, __nv_bfloat16* __restrict__ Vb)
{
    const int row  = blockIdx.x;
    const int d    = threadIdx.x;
    const int lane = d & 31, w = d >> 5;

    __shared__ float sNb[KT_][DD_];
    __shared__ float sEh[DD_];
    __shared__ float sP[KT_];
    __shared__ int   sIdx[KT_];
    __shared__ float sW[KT_];
    __shared__ float sPr[KT_];

    const float eh = eH[(size_t)row * DD_ + d];
    sEh[d] = eh;
    if (d < KT_) { sP[d] = tP[row * KT_ + d]; sIdx[d] = tI[row * KT_ + d]; }
    __syncthreads();

    #pragma unroll
    for (int k = 0; k < KT_; k++) sNb[k][d] = eT[(size_t)sIdx[k] * DD_ + d];
    __syncthreads();

    for (int k = w; k < KT_; k += 8) {
        const float pk = sP[k], ck = 2.f - pk;
        float snb = 0.f, sg = 0.f;
        #pragma unroll
        for (int q = 0; q < 8; q++) {
            const int dd = lane + q * 32;
            const float nb = sNb[k][dd];
            snb += nb;
            sg  += tanhf(ck * sEh[dd] + pk * nb);
        }
        #pragma unroll
        for (int off = 16; off; off >>= 1) {
            snb += __shfl_xor_sync(0xffffffffu, snb, off);
            sg  += __shfl_xor_sync(0xffffffffu, sg,  off);
        }
        if (lane == 0) sW[k] = snb * sg;
    }
    __syncthreads();

    if (d < 32) {
        float val = (d < KT_) ? sW[d] : -CUDART_INF_F;
        float m = val;
        #pragma unroll
        for (int off = 16; off; off >>= 1) m = fmaxf(m, __shfl_xor_sync(0xffffffffu, m, off));
        float ev = (d < KT_) ? expf(val - m) : 0.f;
        float s = ev;
        #pragma unroll
        for (int off = 16; off; off >>= 1) s += __shfl_xor_sync(0xffffffffu, s, off);
        if (d < KT_) sPr[d] = ev / s;
    }
    __syncthreads();

    float acc = 0.f;
    #pragma unroll
    for (int k = 0; k < KT_; k++) acc += sPr[k] * sNb[k][d];

    const float u = eh + acc, vv = eh * acc;
    {
        __nv_bfloat16 h = __float2bfloat16(u);
        __nv_bfloat16 l = __float2bfloat16(u - __bfloat162float(h));
        __nv_bfloat16* rw = Ub + (size_t)row * KA4_;
        rw[d] = h; rw[DD_ + d] = l; rw[2*DD_ + d] = h; rw[3*DD_ + d] = l;
    }
    {
        __nv_bfloat16 h = __float2bfloat16(vv);
        __nv_bfloat16 l = __float2bfloat16(vv - __bfloat162float(h));
        __nv_bfloat16* rw = Vb + (size_t)row * KA4_;
        rw[d] = h; rw[DD_ + d] = l; rw[2*DD_ + d] = h; rw[3*DD_ + d] = l;
    }
}

// ---------------- attention head ---------------------------------------------
__global__ void __launch_bounds__(128) att_kernel(
    const float* __restrict__ E, const float* __restrict__ W1,
    const float* __restrict__ b1, const float* __restrict__ W2,
    const float* __restrict__ b2, float* __restrict__ att)
{
    const int r0 = blockIdx.x * 16;
    const int j  = threadIdx.x;
    __shared__ float sE[16][DD_];
    for (int t = j; t < 16 * DD_; t += 128)
        sE[t >> 8][t & 255] = E[(size_t)(r0 + (t >> 8)) * DD_ + (t & 255)];
    __syncthreads();

    float acc[16];
    #pragma unroll
    for (int r = 0; r < 16; r++) acc[r] = 0.f;
    for (int dd = 0; dd < DD_; dd++) {
        const float wv = W1[dd * 128 + j];
        #pragma unroll
        for (int r = 0; r < 16; r++) acc[r] += sE[r][dd] * wv;
    }
    const float bb = b1[j], w2 = W2[j];
    __shared__ float sRed[16][4];
    const int lane = j & 31, w = j >> 5;
    #pragma unroll
    for (int r = 0; r < 16; r++) {
        float val = acc[r] + bb;
        val = (val > 0.f) ? val : 0.01f * val;
        val *= w2;
        #pragma unroll
        for (int off = 16; off; off >>= 1) val += __shfl_xor_sync(0xffffffffu, val, off);
        if (lane == 0) sRed[r][w] = val;
    }
    __syncthreads();
    if (j < 16) att[r0 + j] = sRed[j][0] + sRed[j][1] + sRed[j][2] + sRed[j][3] + b2[0];
}

// ---------------- softmax-over-nodes reduction -------------------------------
__global__ void __launch_bounds__(1024) smred_kernel(const float* __restrict__ att,
                                                     float* __restrict__ red)
{
    const int tid = threadIdx.x;
    __shared__ float s[32];
    float m = -CUDART_INF_F;
    for (int i = tid; i < NN_; i += 1024) m = fmaxf(m, att[i]);
    #pragma unroll
    for (int off = 16; off; off >>= 1) m = fmaxf(m, __shfl_xor_sync(0xffffffffu, m, off));
    if ((tid & 31) == 0) s[tid >> 5] = m;
    __syncthreads();
    if (tid < 32) {
        float mm = s[tid];
        #pragma unroll
        for (int off = 16; off; off >>= 1) mm = fmaxf(mm, __shfl_xor_sync(0xffffffffu, mm, off));
        if (tid == 0) s[0] = mm;
    }
    __syncthreads();
    const float M = s[0];
    __syncthreads();
    float z = 0.f;
    for (int i = tid; i < NN_; i += 1024) z += expf(att[i] - M);
    #pragma unroll
    for (int off = 16; off; off >>= 1) z += __shfl_xor_sync(0xffffffffu, z, off);
    if ((tid & 31) == 0) s[tid >> 5] = z;
    __syncthreads();
    if (tid < 32) {
        float zz = s[tid];
        #pragma unroll
        for (int off = 16; off; off >>= 1) zz += __shfl_xor_sync(0xffffffffu, zz, off);
        if (tid == 0) { red[0] = M; red[1] = zz; }
    }
}

__global__ void __launch_bounds__(256) egpart_kernel(const float* __restrict__ att,
    const float* __restrict__ E, const float* __restrict__ red, float* __restrict__ part)
{
    const int b = blockIdx.x;
    const int d = threadIdx.x;
    __shared__ float wsh[256];
    wsh[d] = expf(att[b * 256 + d] - red[0]);
    __syncthreads();
    float acc = 0.f;
    const float* Eb = E + (size_t)b * 256 * DD_;
    for (int i = 0; i < 256; i++) acc += wsh[i] * Eb[(size_t)i * DD_ + d];
    part[b * DD_ + d] = acc;
}

__global__ void __launch_bounds__(256) egfin_kernel(const float* __restrict__ part,
    const float* __restrict__ red, float* __restrict__ eg)
{
    const int d = threadIdx.x;
    float s = 0.f;
    #pragma unroll
    for (int b = 0; b < 32; b++) s += part[b * DD_ + d];
    eg[d] = s / red[1];
}

// ---------------- launcher ---------------------------------------------------
extern "C" void kernel_launch(void* const* d_in, const int* in_sizes, int n_in,
                              void* d_out, int out_size)
{
    const float* x    = (const float*)d_in[0];
    const float* Wfc1 = (const float*)d_in[1];
    const float* bfc1 = (const float*)d_in[2];
    const float* Wfc2 = (const float*)d_in[3];
    const float* bfc2 = (const float*)d_in[4];
    const float* Whd  = (const float*)d_in[5];
    const float* bhd  = (const float*)d_in[6];
    const float* Wtl  = (const float*)d_in[7];
    const float* btl  = (const float*)d_in[8];
    const float* Wl1  = (const float*)d_in[9];
    const float* bl1  = (const float*)d_in[10];
    const float* Wl2  = (const float*)d_in[11];
    const float* bl2  = (const float*)d_in[12];
    const float* Wa1  = (const float*)d_in[13];
    const float* ba1  = (const float*)d_in[14];
    const float* Wa2  = (const float*)d_in[15];
    const float* ba2  = (const float*)d_in[16];

    float *P, *eh, *et, *E1, *spill, *att, *red, *part, *tP;
    __nv_bfloat16 *Xbf, *h1b, *hb, *ehs, *ets, *Ub, *Vb;
    __nv_bfloat16 *Wfc1b, *Wfc2b, *Whdb, *Wtlb, *Wl1b, *Wl2b;
    int* tI;
    cudaGetSymbolAddress((void**)&P,     g_P);
    cudaGetSymbolAddress((void**)&eh,    g_eh);
    cudaGetSymbolAddress((void**)&et,    g_et);
    cudaGetSymbolAddress((void**)&E1,    g_E1);
    cudaGetSymbolAddress((void**)&spill, g_spill);
    cudaGetSymbolAddress((void**)&att,   g_att);
    cudaGetSymbolAddress((void**)&red,   g_red);
    cudaGetSymbolAddress((void**)&part,  g_part);
    cudaGetSymbolAddress((void**)&tI,    g_tI);
    cudaGetSymbolAddress((void**)&tP,    g_tP);
    cudaGetSymbolAddress((void**)&Xbf,   g_Xbf);
    cudaGetSymbolAddress((void**)&h1b,   g_h1b);
    cudaGetSymbolAddress((void**)&hb,    g_hb);
    cudaGetSymbolAddress((void**)&ehs,   g_ehs);
    cudaGetSymbolAddress((void**)&ets,   g_ets);
    cudaGetSymbolAddress((void**)&Ub,    g_Ub);
    cudaGetSymbolAddress((void**)&Vb,    g_Vb);
    cudaGetSymbolAddress((void**)&Wfc1b, g_Wfc1b);
    cudaGetSymbolAddress((void**)&Wfc2b, g_Wfc2b);
    cudaGetSymbolAddress((void**)&Whdb,  g_Whdb);
    cudaGetSymbolAddress((void**)&Wtlb,  g_Wtlb);
    cudaGetSymbolAddress((void**)&Wl1b,  g_Wl1b);
    cudaGetSymbolAddress((void**)&Wl2b,  g_Wl2b);

    const int smemNeed = 3 * MMA_STG;
    cudaFuncSetAttribute(attn_mma_kernel,
                         cudaFuncAttributeMaxDynamicSharedMemorySize, smemNeed);
    cudaFuncSetAttribute(mma_gemm_kernel<1, true,  false>,
                         cudaFuncAttributeMaxDynamicSharedMemorySize, smemNeed);
    cudaFuncSetAttribute(mma_gemm_kernel<2, false, false>,
                         cudaFuncAttributeMaxDynamicSharedMemorySize, smemNeed);
    cudaFuncSetAttribute(mma_gemm_kernel<3, false, false>,
                         cudaFuncAttributeMaxDynamicSharedMemorySize, smemNeed);
    cudaFuncSetAttribute(mma_gemm_kernel<0, true,  false>,
                         cudaFuncAttributeMaxDynamicSharedMemorySize, smemNeed);
    cudaFuncSetAttribute(mma_gemm_kernel<0, true,  true>,
                         cudaFuncAttributeMaxDynamicSharedMemorySize, smemNeed);

    float* out = (float*)d_out;
    const size_t ND = (size_t)NN_ * DD_;
    float* e_out;
    float* eg_out;
    if ((size_t)out_size >= ND + DD_)      { e_out = out;   eg_out = out + ND; }
    else if ((size_t)out_size >= ND)       { e_out = out;   eg_out = nullptr;  }
    else                                   { e_out = spill; eg_out = out;      }

    const dim3 gG(2, 64);
    const dim3 gA(64, 64);

    // prep: input + all weight splits
    xsplit_kernel<<<NN_, 256>>>(x, Xbf);
    wprep6_kernel<<<DIN_ + 5 * DD_, 256>>>(Wfc1, Wfc2, Whd, Wtl, Wl1, Wl2,
                                           Wfc1b, Wfc2b, Whdb, Wtlb, Wl1b, Wl2b);

    // trunk on tensor cores (4-term split, fp32-accurate)
    mma_gemm_kernel<1, true,  false><<<gG, 512, smemNeed>>>(Xbf, Wfc1b, bfc1, nullptr, nullptr, h1b, KAX_, 0.f);
    mma_gemm_kernel<1, true,  false><<<gG, 512, smemNeed>>>(h1b, Wfc2b, bfc2, nullptr, nullptr, hb,  KA4_, 0.f);
    mma_gemm_kernel<2, false, false><<<gG, 512, smemNeed>>>(hb,  Whdb,  bhd,  nullptr, eh,      ehs, KA4_, 0.0625f);
    mma_gemm_kernel<3, false, false><<<gG, 512, smemNeed>>>(hb,  Wtlb,  btl,  nullptr, et,      ets, KA4_, 0.f);

    // pairwise logits (3-term split) + top-k + neighbor aggregation
    attn_mma_kernel<<<gA, 512, smemNeed>>>(ehs, ets, P);
    topk_kernel    <<<NN_, 256>>>(P, tI, tP);
    neighbor_kernel<<<NN_, 256>>>(eh, et, tI, tP, Ub, Vb);

    // e = relu(U@Wl1+b) + relu(V@Wl2+b)
    mma_gemm_kernel<0, true, false><<<gG, 512, smemNeed>>>(Ub, Wl1b, bl1, nullptr, E1,    nullptr, KA4_, 0.f);
    mma_gemm_kernel<0, true, true ><<<gG, 512, smemNeed>>>(Vb, Wl2b, bl2, E1,      e_out, nullptr, KA4_, 0.f);

    if (eg_out) {
        att_kernel   <<<NN_ / 16, 128>>>(e_out, Wa1, ba1, Wa2, ba2, att);
        smred_kernel <<<1, 1024>>>(att, red);
        egpart_kernel<<<32, 256>>>(att, e_out, red, part);
        egfin_kernel <<<1, 256>>>(part, red, eg_out);
    }
}

// round 9
// speedup vs baseline: 1.3109x; 1.0368x over previous
#include <cuda_runtime.h>
#include <cuda_bf16.h>
#include <math_constants.h>
#include <cstdint>

#define NN_  8192
#define DIN_ 1024
#define DD_  256
#define KT_  30
#define KA3_ 768
#define KA4_ 1024
#define KAX_ 4096

// ---------------- scratch ----------------------------------------------------
__device__ float g_P[(size_t)NN_ * NN_];
__device__ float g_eh[NN_ * DD_];
__device__ float g_et[NN_ * DD_];
__device__ float g_E1[NN_ * DD_];
__device__ float g_spill[NN_ * DD_];
__device__ __nv_bfloat16 g_Xbf [(size_t)NN_ * KAX_];
__device__ __nv_bfloat16 g_h1b [(size_t)NN_ * KA4_];
__device__ __nv_bfloat16 g_hb  [(size_t)NN_ * KA4_];
__device__ __nv_bfloat16 g_ehs [(size_t)NN_ * KA3_];
__device__ __nv_bfloat16 g_ets [(size_t)NN_ * KA3_];
__device__ __nv_bfloat16 g_Ub  [(size_t)NN_ * KA4_];
__device__ __nv_bfloat16 g_Vb  [(size_t)NN_ * KA4_];
__device__ __nv_bfloat16 g_Wfc1b[(size_t)DD_ * KAX_];
__device__ __nv_bfloat16 g_Wfc2b[DD_ * KA4_];
__device__ __nv_bfloat16 g_Whdb [DD_ * KA4_];
__device__ __nv_bfloat16 g_Wtlb [DD_ * KA4_];
__device__ __nv_bfloat16 g_Wl1b [DD_ * KA4_];
__device__ __nv_bfloat16 g_Wl2b [DD_ * KA4_];
__device__ int   g_tI[NN_ * KT_];
__device__ float g_tP[NN_ * KT_];
__device__ float g_att[NN_];
__device__ float g_red[2];
__device__ float g_part[32 * DD_];

// =================== warp-MMA helpers ========================================
__device__ __forceinline__ uint32_t smem_u32(const void* p) {
    uint32_t a;
    asm("{ .reg .u64 t; cvta.to.shared.u64 t, %1; cvt.u32.u64 %0, t; }" : "=r"(a) : "l"(p));
    return a;
}
#define SW128(off) ((off) ^ (((off) >> 3) & 0x70))
#define CP16(dst, src)    asm volatile("cp.async.cg.shared.global [%0], [%1], 16;" :: "r"(dst), "l"(src) : "memory")
#define CP_COMMIT()       asm volatile("cp.async.commit_group;" ::: "memory")

__device__ __forceinline__ void ldsm4(uint32_t* r, uint32_t addr) {
    asm volatile("ldmatrix.sync.aligned.m8n8.x4.shared.b16 {%0,%1,%2,%3}, [%4];"
        : "=r"(r[0]), "=r"(r[1]), "=r"(r[2]), "=r"(r[3]) : "r"(addr));
}
__device__ __forceinline__ void mma16816(float* d, const uint32_t* a, const uint32_t* b) {
    asm volatile("mma.sync.aligned.m16n8k16.row.col.f32.bf16.bf16.f32 "
        "{%0,%1,%2,%3}, {%4,%5,%6,%7}, {%8,%9}, {%0,%1,%2,%3};"
        : "+f"(d[0]), "+f"(d[1]), "+f"(d[2]), "+f"(d[3])
        : "r"(a[0]), "r"(a[1]), "r"(a[2]), "r"(a[3]), "r"(b[0]), "r"(b[1]));
}

// ---------------- prep --------------------------------------------------------
__global__ void __launch_bounds__(256) xsplit_kernel(const float* __restrict__ x,
                                                     __nv_bfloat16* __restrict__ X)
{
    const int r = blockIdx.x;
    #pragma unroll
    for (int q = 0; q < 4; q++) {
        const int c = threadIdx.x + q * 256;
        float v = x[(size_t)r * DIN_ + c];
        __nv_bfloat16 h = __float2bfloat16(v);
        __nv_bfloat16 l = __float2bfloat16(v - __bfloat162float(h));
        __nv_bfloat16* row = X + (size_t)r * KAX_;
        row[c] = h; row[DIN_ + c] = l; row[2*DIN_ + c] = h; row[3*DIN_ + c] = l;
    }
}
__global__ void __launch_bounds__(256) wprep6_kernel(
    const float* __restrict__ W1, const float* __restrict__ W2,
    const float* __restrict__ W3, const float* __restrict__ W4,
    const float* __restrict__ W5, const float* __restrict__ W6,
    __nv_bfloat16* __restrict__ B1, __nv_bfloat16* __restrict__ B2,
    __nv_bfloat16* __restrict__ B3, __nv_bfloat16* __restrict__ B4,
    __nv_bfloat16* __restrict__ B5, __nv_bfloat16* __restrict__ B6)
{
    int bid = blockIdx.x;
    const float* W; __nv_bfloat16* B; int K, k;
    if (bid < 1024)      { W = W1; B = B1; K = DIN_; k = bid; }
    else {
        bid -= 1024;
        const int s = bid >> 8;
        k = bid & 255; K = DD_;
        switch (s) {
            case 0: W = W2; B = B2; break;
            case 1: W = W3; B = B3; break;
            case 2: W = W4; B = B4; break;
            case 3: W = W5; B = B5; break;
            default: W = W6; B = B6; break;
        }
    }
    const int n = threadIdx.x;
    float v = W[(size_t)k * DD_ + n];
    __nv_bfloat16 h = __float2bfloat16(v);
    __nv_bfloat16 l = __float2bfloat16(v - __bfloat162float(h));
    __nv_bfloat16* row = B + (size_t)n * (4 * K);
    row[k] = h; row[K + k] = h; row[2*K + k] = l; row[3*K + k] = l;
}

#define MMA_STG 32768

// ---------------- tile fill, 512-thread version ------------------------------
__device__ __forceinline__ void tile_fill(uint32_t sbase, int kc, int bm, int bn,
    const __nv_bfloat16* __restrict__ Ag, const __nv_bfloat16* __restrict__ Bg,
    int tid, int Ka)
{
    #pragma unroll
    for (int i = 0; i < 2; i++) {
        int q = tid + i * 512;
        int row = q >> 3, c = q & 7;
        const __nv_bfloat16* src = Ag + (size_t)(bm * 128 + row) * Ka + kc * 64 + c * 8;
        CP16(sbase + SW128((uint32_t)(row * 128 + c * 16)), src);
    }
    #pragma unroll
    for (int i = 0; i < 2; i++) {
        int q = tid + i * 512;
        int row = q >> 3, c = q & 7;
        const __nv_bfloat16* src = Bg + (size_t)(bn * 128 + row) * Ka + kc * 64 + c * 8;
        CP16(sbase + 16384 + SW128((uint32_t)(row * 128 + c * 16)), src);
    }
}
// ---------------- tile fill, 256-thread version ------------------------------
__device__ __forceinline__ void tile_fill8(uint32_t sbase, int kc, int bm, int bn,
    const __nv_bfloat16* __restrict__ Ag, const __nv_bfloat16* __restrict__ Bg,
    int tid, int Ka)
{
    #pragma unroll
    for (int i = 0; i < 4; i++) {
        int q = tid + i * 256;
        int row = q >> 3, c = q & 7;
        const __nv_bfloat16* src = Ag + (size_t)(bm * 128 + row) * Ka + kc * 64 + c * 8;
        CP16(sbase + SW128((uint32_t)(row * 128 + c * 16)), src);
    }
    #pragma unroll
    for (int i = 0; i < 4; i++) {
        int q = tid + i * 256;
        int row = q >> 3, c = q & 7;
        const __nv_bfloat16* src = Bg + (size_t)(bn * 128 + row) * Ka + kc * 64 + c * 8;
        CP16(sbase + 16384 + SW128((uint32_t)(row * 128 + c * 16)), src);
    }
}

// ---------------- 16-warp mainloop (trunk GEMMs) -----------------------------
struct MmaAcc { float a[2][4][4]; };

__device__ __forceinline__ void mma_mainloop(MmaAcc& A_, uint32_t sb, int nchunk,
    int bm, int bn, const __nv_bfloat16* Ag, const __nv_bfloat16* Bg, int Ka,
    int tid, int wid, int lane)
{
    const int wm = (wid & 3) * 32;
    const int wn = (wid >> 2) * 32;
    const int aRow = (lane & 15);
    const int aKb  = (lane >> 4) * 16;
    const int bRow = ((lane >> 4) << 3) + (lane & 7);
    const int bKb  = ((lane >> 3) & 1) * 16;

    uint32_t aOff[2], bOff[2];
    aOff[0] = SW128((uint32_t)((wm +      aRow) * 128 + aKb));
    aOff[1] = SW128((uint32_t)((wm + 16 + aRow) * 128 + aKb));
    bOff[0] = SW128((uint32_t)((wn +      bRow) * 128 + bKb)) + 16384u;
    bOff[1] = SW128((uint32_t)((wn + 16 + bRow) * 128 + bKb)) + 16384u;

    tile_fill(sb,           0, bm, bn, Ag, Bg, tid, Ka);
    CP_COMMIT();
    tile_fill(sb + MMA_STG, 1, bm, bn, Ag, Bg, tid, Ka);
    CP_COMMIT();

    int sidx = 0;
    for (int c = 0; c < nchunk; c++) {
        asm volatile("cp.async.wait_group 1;" ::: "memory");
        __syncthreads();

        if (c + 2 < nchunk) {
            int s2 = sidx + 2; if (s2 >= 3) s2 -= 3;
            tile_fill(sb + s2 * MMA_STG, c + 2, bm, bn, Ag, Bg, tid, Ka);
            CP_COMMIT();
        }

        const uint32_t stg = sb + sidx * MMA_STG;
        uint32_t abuf[2][2][4], bbuf[2][2][4];
        ldsm4(abuf[0][0], stg + aOff[0]);
        ldsm4(abuf[0][1], stg + aOff[1]);
        ldsm4(bbuf[0][0], stg + bOff[0]);
        ldsm4(bbuf[0][1], stg + bOff[1]);
        #pragma unroll
        for (int ks = 0; ks < 4; ks++) {
            const int cur = ks & 1, nxt = cur ^ 1;
            if (ks < 3) {
                const uint32_t x = (uint32_t)(ks + 1) << 5;
                ldsm4(abuf[nxt][0], (stg + aOff[0]) ^ x);
                ldsm4(abuf[nxt][1], (stg + aOff[1]) ^ x);
                ldsm4(bbuf[nxt][0], (stg + bOff[0]) ^ x);
                ldsm4(bbuf[nxt][1], (stg + bOff[1]) ^ x);
            }
            #pragma unroll
            for (int mt = 0; mt < 2; mt++)
                #pragma unroll
                for (int n8 = 0; n8 < 4; n8++)
                    mma16816(A_.a[mt][n8], abuf[cur][mt], &bbuf[cur][n8 >> 1][(n8 & 1) * 2]);
        }
        if (++sidx == 3) sidx = 0;
    }
}

// ---------------- 8-warp mainloop (attn GEMM, 2 CTA/SM) ----------------------
struct MmaAcc8 { float a[2][8][4]; };

__device__ __forceinline__ void mma_mainloop8(MmaAcc8& A_, uint32_t sb, int nchunk,
    int bm, int bn, const __nv_bfloat16* Ag, const __nv_bfloat16* Bg, int Ka,
    int tid, int wid, int lane)
{
    const int wm = (wid & 3) * 32;      // 4 m-warps
    const int wn = (wid >> 2) * 64;     // 2 n-warps
    const int aRow = (lane & 15);
    const int aKb  = (lane >> 4) * 16;
    const int bRow = ((lane >> 4) << 3) + (lane & 7);
    const int bKb  = ((lane >> 3) & 1) * 16;

    uint32_t aOff[2], bOff[4];
    aOff[0] = SW128((uint32_t)((wm +      aRow) * 128 + aKb));
    aOff[1] = SW128((uint32_t)((wm + 16 + aRow) * 128 + aKb));
    #pragma unroll
    for (int nt = 0; nt < 4; nt++)
        bOff[nt] = SW128((uint32_t)((wn + nt * 16 + bRow) * 128 + bKb)) + 16384u;

    tile_fill8(sb,           0, bm, bn, Ag, Bg, tid, Ka);
    CP_COMMIT();
    tile_fill8(sb + MMA_STG, 1, bm, bn, Ag, Bg, tid, Ka);
    CP_COMMIT();

    int sidx = 0;
    for (int c = 0; c < nchunk; c++) {
        asm volatile("cp.async.wait_group 1;" ::: "memory");
        __syncthreads();

        if (c + 2 < nchunk) {
            int s2 = sidx + 2; if (s2 >= 3) s2 -= 3;
            tile_fill8(sb + s2 * MMA_STG, c + 2, bm, bn, Ag, Bg, tid, Ka);
            CP_COMMIT();
        }

        const uint32_t stg = sb + sidx * MMA_STG;
        uint32_t abuf[2][2][4], bbuf[2][4][4];
        ldsm4(abuf[0][0], stg + aOff[0]);
        ldsm4(abuf[0][1], stg + aOff[1]);
        #pragma unroll
        for (int nt = 0; nt < 4; nt++) ldsm4(bbuf[0][nt], stg + bOff[nt]);
        #pragma unroll
        for (int ks = 0; ks < 4; ks++) {
            const int cur = ks & 1, nxt = cur ^ 1;
            if (ks < 3) {
                const uint32_t x = (uint32_t)(ks + 1) << 5;
                ldsm4(abuf[nxt][0], (stg + aOff[0]) ^ x);
                ldsm4(abuf[nxt][1], (stg + aOff[1]) ^ x);
                #pragma unroll
                for (int nt = 0; nt < 4; nt++)
                    ldsm4(bbuf[nxt][nt], (stg + bOff[nt]) ^ x);
            }
            #pragma unroll
            for (int mt = 0; mt < 2; mt++)
                #pragma unroll
                for (int n8 = 0; n8 < 8; n8++)
                    mma16816(A_.a[mt][n8], abuf[cur][mt], &bbuf[cur][n8 >> 1][(n8 & 1) * 2]);
        }
        if (++sidx == 3) sidx = 0;
    }
}

// ---------------- attn GEMM: P = ehs(A3) @ ets(B3)^T --------------------------
__global__ void __launch_bounds__(256, 2) attn_mma_kernel(
    const __nv_bfloat16* __restrict__ Ag, const __nv_bfloat16* __restrict__ Bg,
    float* __restrict__ P)
{
    extern __shared__ char smem[];
    const uint32_t sb = smem_u32(smem);
    const int tid = threadIdx.x, wid = tid >> 5, lane = tid & 31;
    const int bn = blockIdx.x, bm = blockIdx.y;

    MmaAcc8 acc;
    #pragma unroll
    for (int i = 0; i < 2; i++)
        #pragma unroll
        for (int j = 0; j < 8; j++)
            #pragma unroll
            for (int q = 0; q < 4; q++) acc.a[i][j][q] = 0.f;

    mma_mainloop8(acc, sb, KA3_ / 64, bm, bn, Ag, Bg, KA3_, tid, wid, lane);

    const int wm = (wid & 3) * 32, wn = (wid >> 2) * 64;
    const int tig = lane & 3, gid = lane >> 2;
    #pragma unroll
    for (int mt = 0; mt < 2; mt++) {
        const int r0 = bm * 128 + wm + mt * 16 + gid;
        #pragma unroll
        for (int n8 = 0; n8 < 8; n8++) {
            const int cc = bn * 128 + wn + n8 * 8 + tig * 2;
            *reinterpret_cast<float2*>(P + (size_t)r0 * NN_ + cc)
                = make_float2(acc.a[mt][n8][0], acc.a[mt][n8][1]);
            *reinterpret_cast<float2*>(P + (size_t)(r0 + 8) * NN_ + cc)
                = make_float2(acc.a[mt][n8][2], acc.a[mt][n8][3]);
        }
    }
}

// ---------------- trunk GEMM with fused split epilogues ----------------------
template<int OSPL, bool RELU, bool HASADD>
__global__ void __launch_bounds__(512, 1) mma_gemm_kernel(
    const __nv_bfloat16* __restrict__ Ag, const __nv_bfloat16* __restrict__ Bg,
    const float* __restrict__ bias, const float* __restrict__ addend,
    float* __restrict__ C, __nv_bfloat16* __restrict__ S, int Ka, float scale)
{
    extern __shared__ char smem[];
    const uint32_t sb = smem_u32(smem);
    const int tid = threadIdx.x, wid = tid >> 5, lane = tid & 31;
    const int bn = blockIdx.x, bm = blockIdx.y;

    MmaAcc acc;
    #pragma unroll
    for (int i = 0; i < 2; i++)
        #pragma unroll
        for (int j = 0; j < 4; j++)
            #pragma unroll
            for (int q = 0; q < 4; q++) acc.a[i][j][q] = 0.f;

    mma_mainloop(acc, sb, Ka / 64, bm, bn, Ag, Bg, Ka, tid, wid, lane);

    const int wm = (wid & 3) * 32, wn = (wid >> 2) * 32;
    const int tig = lane & 3, gid = lane >> 2;
    #pragma unroll
    for (int mt = 0; mt < 2; mt++) {
        #pragma unroll
        for (int n8 = 0; n8 < 4; n8++) {
            const int cc = bn * 128 + wn + n8 * 8 + tig * 2;
            #pragma unroll
            for (int hh = 0; hh < 2; hh++) {
                const int r = bm * 128 + wm + mt * 16 + gid + hh * 8;
                #pragma unroll
                for (int e = 0; e < 2; e++) {
                    const int c = cc + e;
                    float v = acc.a[mt][n8][hh * 2 + e] + bias[c];
                    if (RELU)   v = fmaxf(v, 0.f);
                    if (HASADD) v += addend[(size_t)r * DD_ + c];
                    if (C) C[(size_t)r * DD_ + c] = v;
                    if (OSPL == 1) {
                        __nv_bfloat16 h = __float2bfloat16(v);
                        __nv_bfloat16 l = __float2bfloat16(v - __bfloat162float(h));
                        __nv_bfloat16* row = S + (size_t)r * KA4_;
                        row[c] = h; row[DD_ + c] = l; row[2*DD_ + c] = h; row[3*DD_ + c] = l;
                    } else if (OSPL == 2) {
                        float vs = v * scale;
                        __nv_bfloat16 h = __float2bfloat16(vs);
                        __nv_bfloat16 l = __float2bfloat16(vs - __bfloat162float(h));
                        __nv_bfloat16* row = S + (size_t)r * KA3_;
                        row[c] = h; row[DD_ + c] = l; row[2*DD_ + c] = h;
                    } else if (OSPL == 3) {
                        __nv_bfloat16 h = __float2bfloat16(v);
                        __nv_bfloat16 l = __float2bfloat16(v - __bfloat162float(h));
                        __nv_bfloat16* row = S + (size_t)r * KA3_;
                        row[c] = h; row[DD_ + c] = h; row[2*DD_ + c] = l;
                    }
                }
            }
        }
    }
}

// ---------------- per-row top-30 via 12-bit radix select ----------------------
#define TK_CAP 512
__global__ void __launch_bounds__(256) topk_kernel(const float* __restrict__ P,
                                                   int* __restrict__ tI,
                                                   float* __restrict__ tP)
{
    const int row  = blockIdx.x;
    const int tid  = threadIdx.x;
    const int lane = tid & 31, w = tid >> 5;
    const float* p = P + (size_t)row * NN_;

    float v[32];
    uint32_t key[32];
    #pragma unroll
    for (int j = 0; j < 32; j++) {
        v[j] = p[tid + j * 256];
        uint32_t u = __float_as_uint(v[j]);
        key[j] = (u & 0x80000000u) ? ~u : (u | 0x80000000u);
    }

    __shared__ int   hist[4096];
    __shared__ int   part[256];
    __shared__ int   sPivot[4];          // [0]=pivot bin, [1]=nAbove, [2]=fallback flag
    __shared__ float sV[KT_];
    __shared__ int   sI[KT_];
    __shared__ float cV[TK_CAP];
    __shared__ int   cI[TK_CAP];
    __shared__ int   cnts[2];

    #pragma unroll
    for (int i = 0; i < 16; i++) hist[tid * 16 + i] = 0;
    if (tid < 2) cnts[tid] = 0;
    __syncthreads();

    #pragma unroll
    for (int j = 0; j < 32; j++) atomicAdd(&hist[key[j] >> 20], 1);
    __syncthreads();

    {
        int s = 0;
        #pragma unroll
        for (int i = 0; i < 16; i++) s += hist[tid * 16 + i];
        part[tid] = s;
    }
    __syncthreads();
    if (tid == 0) {
        int acc = 0, t = 255;
        for (; t >= 0; t--) { acc += part[t]; if (acc >= KT_) break; }
        int cntAbove = acc - part[t];
        int b = -1;
        for (int bin = t * 16 + 15; bin >= t * 16; bin--) {
            int h = hist[bin];
            if (cntAbove + h >= KT_) { b = bin; break; }
            cntAbove += h;
        }
        sPivot[0] = b; sPivot[1] = cntAbove;
        sPivot[2] = 0;
    }
    __syncthreads();

    const uint32_t pb = (uint32_t)sPivot[0];
    const int nAbove  = sPivot[1];

    #pragma unroll
    for (int j = 0; j < 32; j++) {
        uint32_t bin = key[j] >> 20;
        if (bin > pb) {
            int pos = atomicAdd(&cnts[0], 1);
            sV[pos] = v[j]; sI[pos] = tid + j * 256;
        } else if (bin == pb) {
            int pos = atomicAdd(&cnts[1], 1);
            if (pos < TK_CAP) { cV[pos] = v[j]; cI[pos] = tid + j * 256; }
            else sPivot[2] = 1;
        }
    }
    __syncthreads();

    if (sPivot[2] == 0) {
        // warp 0: pick (30 - nAbove) from pivot-bin candidates by (value desc, idx asc)
        if (tid < 32) {
            const int ncand = min(cnts[1], TK_CAP);
            const int need  = KT_ - nAbove;
            float mv[16]; int mi[16];
            #pragma unroll
            for (int q = 0; q < 16; q++) {
                int idx = tid + q * 32;
                if (idx < ncand) { mv[q] = cV[idx]; mi[q] = cI[idx]; }
                else             { mv[q] = -CUDART_INF_F; mi[q] = 0x7fffffff; }
            }
            for (int it = 0; it < need; it++) {
                float bv = mv[0]; int bi = mi[0], bq = 0;
                #pragma unroll
                for (int q = 1; q < 16; q++)
                    if (mv[q] > bv || (mv[q] == bv && mi[q] < bi)) { bv = mv[q]; bi = mi[q]; bq = q; }
                float wv = bv; int wi = bi;
                #pragma unroll
                for (int off = 16; off; off >>= 1) {
                    float ov = __shfl_xor_sync(0xffffffffu, wv, off);
                    int   oi = __shfl_xor_sync(0xffffffffu, wi, off);
                    if (ov > wv || (ov == wv && oi < wi)) { wv = ov; wi = oi; }
                }
                // winner lane (unique by index) appends + invalidates its slot
                if (bi == wi && bv == wv && bi != 0x7fffffff) {
                    sV[nAbove + it] = wv; sI[nAbove + it] = wi;
                    mv[bq] = -CUDART_INF_F; mi[bq] = 0x7fffffff;
                }
                __syncwarp();
            }
        }
        __syncthreads();
    } else {
        // degenerate fallback: exact iterative argmax
        __syncthreads();
        __shared__ float fV[8]; __shared__ int fI[9];
        float bv = v[0]; int bj = 0;
        #pragma unroll
        for (int j = 1; j < 32; j++) if (v[j] > bv) { bv = v[j]; bj = j; }
        for (int it = 0; it < KT_; it++) {
            float wv = bv; int wi = tid + bj * 256;
            #pragma unroll
            for (int off = 16; off; off >>= 1) {
                float ov = __shfl_xor_sync(0xffffffffu, wv, off);
                int   oi = __shfl_xor_sync(0xffffffffu, wi, off);
                if (ov > wv || (ov == wv && oi < wi)) { wv = ov; wi = oi; }
            }
            if (lane == 0) { fV[w] = wv; fI[w] = wi; }
            __syncthreads();
            if (tid == 0) {
                float Bv = fV[0]; int Bi = fI[0];
                #pragma unroll
                for (int q = 1; q < 8; q++)
                    if (fV[q] > Bv || (fV[q] == Bv && fI[q] < Bi)) { Bv = fV[q]; Bi = fI[q]; }
                sV[it] = Bv; sI[it] = Bi; fI[8] = Bi;
            }
            __syncthreads();
            const int win = fI[8];
            if ((win & 255) == tid) {
                v[win >> 8] = -CUDART_INF_F;
                bv = v[0]; bj = 0;
                #pragma unroll
                for (int j = 1; j < 32; j++) if (v[j] > bv) { bv = v[j]; bj = j; }
            }
        }
        __syncthreads();
    }

    // softmax over the 30 selected values (order-independent downstream)
    if (tid < 32) {
        float val = (tid < KT_) ? sV[tid] : -CUDART_INF_F;
        float m = val;
        #pragma unroll
        for (int off = 16; off; off >>= 1) m = fmaxf(m, __shfl_xor_sync(0xffffffffu, m, off));
        float ev = (tid < KT_) ? expf(val - m) : 0.f;
        float s = ev;
        #pragma unroll
        for (int off = 16; off; off >>= 1) s += __shfl_xor_sync(0xffffffffu, s, off);
        if (tid < KT_) {
            tP[row * KT_ + tid] = ev / s;
            tI[row * KT_ + tid] = sI[tid];
        }
    }
}

// ---------------- fused neighbor aggregation ---------------------------------
__global__ void __launch_bounds__(256) neighbor_kernel(
    const float* __restrict__ eH, const float* __restrict__ eT,
    const int* __restrict__ tI, const float* __restrict__ tP,
    __nv_bfloat16* __restrict__ Ub, __nv_bfloat16* __restrict__ Vb)
{
    const int row  = blockIdx.x;
    const int d    = threadIdx.x;
    const int lane = d & 31, w = d >> 5;

    __shared__ float sNb[KT_][DD_];
    __shared__ float sEh[DD_];
    __shared__ float sP[KT_];
    __shared__ int   sIdx[KT_];
    __shared__ float sW[KT_];
    __shared__ float sPr[KT_];

    const float eh = eH[(size_t)row * DD_ + d];
    sEh[d] = eh;
    if (d < KT_) { sP[d] = tP[row * KT_ + d]; sIdx[d] = tI[row * KT_ + d]; }
    __syncthreads();

    #pragma unroll
    for (int k = 0; k < KT_; k++) sNb[k][d] = eT[(size_t)sIdx[k] * DD_ + d];
    __syncthreads();

    for (int k = w; k < KT_; k += 8) {
        const float pk = sP[k], ck = 2.f - pk;
        float snb = 0.f, sg = 0.f;
        #pragma unroll
        for (int q = 0; q < 8; q++) {
            const int dd = lane + q * 32;
            const float nb = sNb[k][dd];
            snb += nb;
            sg  += tanhf(ck * sEh[dd] + pk * nb);
        }
        #pragma unroll
        for (int off = 16; off; off >>= 1) {
            snb += __shfl_xor_sync(0xffffffffu, snb, off);
            sg  += __shfl_xor_sync(0xffffffffu, sg,  off);
        }
        if (lane == 0) sW[k] = snb * sg;
    }
    __syncthreads();

    if (d < 32) {
        float val = (d < KT_) ? sW[d] : -CUDART_INF_F;
        float m = val;
        #pragma unroll
        for (int off = 16; off; off >>= 1) m = fmaxf(m, __shfl_xor_sync(0xffffffffu, m, off));
        float ev = (d < KT_) ? expf(val - m) : 0.f;
        float s = ev;
        #pragma unroll
        for (int off = 16; off; off >>= 1) s += __shfl_xor_sync(0xffffffffu, s, off);
        if (d < KT_) sPr[d] = ev / s;
    }
    __syncthreads();

    float acc = 0.f;
    #pragma unroll
    for (int k = 0; k < KT_; k++) acc += sPr[k] * sNb[k][d];

    const float u = eh + acc, vv = eh * acc;
    {
        __nv_bfloat16 h = __float2bfloat16(u);
        __nv_bfloat16 l = __float2bfloat16(u - __bfloat162float(h));
        __nv_bfloat16* rw = Ub + (size_t)row * KA4_;
        rw[d] = h; rw[DD_ + d] = l; rw[2*DD_ + d] = h; rw[3*DD_ + d] = l;
    }
    {
        __nv_bfloat16 h = __float2bfloat16(vv);
        __nv_bfloat16 l = __float2bfloat16(vv - __bfloat162float(h));
        __nv_bfloat16* rw = Vb + (size_t)row * KA4_;
        rw[d] = h; rw[DD_ + d] = l; rw[2*DD_ + d] = h; rw[3*DD_ + d] = l;
    }
}

// ---------------- attention head ----------------------------------------------
__global__ void __launch_bounds__(128) att_kernel(
    const float* __restrict__ E, const float* __restrict__ W1,
    const float* __restrict__ b1, const float* __restrict__ W2,
    const float* __restrict__ b2, float* __restrict__ att)
{
    const int r0 = blockIdx.x * 16;
    const int j  = threadIdx.x;
    __shared__ float sE[16][DD_];
    for (int t = j; t < 16 * DD_; t += 128)
        sE[t >> 8][t & 255] = E[(size_t)(r0 + (t >> 8)) * DD_ + (t & 255)];
    __syncthreads();

    float acc[16];
    #pragma unroll
    for (int r = 0; r < 16; r++) acc[r] = 0.f;
    for (int dd = 0; dd < DD_; dd++) {
        const float wv = W1[dd * 128 + j];
        #pragma unroll
        for (int r = 0; r < 16; r++) acc[r] += sE[r][dd] * wv;
    }
    const float bb = b1[j], w2 = W2[j];
    __shared__ float sRed[16][4];
    const int lane = j & 31, w = j >> 5;
    #pragma unroll
    for (int r = 0; r < 16; r++) {
        float val = acc[r] + bb;
        val = (val > 0.f) ? val : 0.01f * val;
        val *= w2;
        #pragma unroll
        for (int off = 16; off; off >>= 1) val += __shfl_xor_sync(0xffffffffu, val, off);
        if (lane == 0) sRed[r][w] = val;
    }
    __syncthreads();
    if (j < 16) att[r0 + j] = sRed[j][0] + sRed[j][1] + sRed[j][2] + sRed[j][3] + b2[0];
}

// ---------------- softmax-over-nodes reduction --------------------------------
__global__ void __launch_bounds__(1024) smred_kernel(const float* __restrict__ att,
                                                     float* __restrict__ red)
{
    const int tid = threadIdx.x;
    __shared__ float s[32];
    float m = -CUDART_INF_F;
    for (int i = tid; i < NN_; i += 1024) m = fmaxf(m, att[i]);
    #pragma unroll
    for (int off = 16; off; off >>= 1) m = fmaxf(m, __shfl_xor_sync(0xffffffffu, m, off));
    if ((tid & 31) == 0) s[tid >> 5] = m;
    __syncthreads();
    if (tid < 32) {
        float mm = s[tid];
        #pragma unroll
        for (int off = 16; off; off >>= 1) mm = fmaxf(mm, __shfl_xor_sync(0xffffffffu, mm, off));
        if (tid == 0) s[0] = mm;
    }
    __syncthreads();
    const float M = s[0];
    __syncthreads();
    float z = 0.f;
    for (int i = tid; i < NN_; i += 1024) z += expf(att[i] - M);
    #pragma unroll
    for (int off = 16; off; off >>= 1) z += __shfl_xor_sync(0xffffffffu, z, off);
    if ((tid & 31) == 0) s[tid >> 5] = z;
    __syncthreads();
    if (tid < 32) {
        float zz = s[tid];
        #pragma unroll
        for (int off = 16; off; off >>= 1) zz += __shfl_xor_sync(0xffffffffu, zz, off);
        if (tid == 0) { red[0] = M; red[1] = zz; }
    }
}

__global__ void __launch_bounds__(256) egpart_kernel(const float* __restrict__ att,
    const float* __restrict__ E, const float* __restrict__ red, float* __restrict__ part)
{
    const int b = blockIdx.x;
    const int d = threadIdx.x;
    __shared__ float wsh[256];
    wsh[d] = expf(att[b * 256 + d] - red[0]);
    __syncthreads();
    float acc = 0.f;
    const float* Eb = E + (size_t)b * 256 * DD_;
    for (int i = 0; i < 256; i++) acc += wsh[i] * Eb[(size_t)i * DD_ + d];
    part[b * DD_ + d] = acc;
}

__global__ void __launch_bounds__(256) egfin_kernel(const float* __restrict__ part,
    const float* __restrict__ red, float* __restrict__ eg)
{
    const int d = threadIdx.x;
    float s = 0.f;
    #pragma unroll
    for (int b = 0; b < 32; b++) s += part[b * DD_ + d];
    eg[d] = s / red[1];
}

// ---------------- launcher -----------------------------------------------------
extern "C" void kernel_launch(void* const* d_in, const int* in_sizes, int n_in,
                              void* d_out, int out_size)
{
    const float* x    = (const float*)d_in[0];
    const float* Wfc1 = (const float*)d_in[1];
    const float* bfc1 = (const float*)d_in[2];
    const float* Wfc2 = (const float*)d_in[3];
    const float* bfc2 = (const float*)d_in[4];
    const float* Whd  = (const float*)d_in[5];
    const float* bhd  = (const float*)d_in[6];
    const float* Wtl  = (const float*)d_in[7];
    const float* btl  = (const float*)d_in[8];
    const float* Wl1  = (const float*)d_in[9];
    const float* bl1  = (const float*)d_in[10];
    const float* Wl2  = (const float*)d_in[11];
    const float* bl2  = (const float*)d_in[12];
    const float* Wa1  = (const float*)d_in[13];
    const float* ba1  = (const float*)d_in[14];
    const float* Wa2  = (const float*)d_in[15];
    const float* ba2  = (const float*)d_in[16];

    float *P, *eh, *et, *E1, *spill, *att, *red, *part, *tP;
    __nv_bfloat16 *Xbf, *h1b, *hb, *ehs, *ets, *Ub, *Vb;
    __nv_bfloat16 *Wfc1b, *Wfc2b, *Whdb, *Wtlb, *Wl1b, *Wl2b;
    int* tI;
    cudaGetSymbolAddress((void**)&P,     g_P);
    cudaGetSymbolAddress((void**)&eh,    g_eh);
    cudaGetSymbolAddress((void**)&et,    g_et);
    cudaGetSymbolAddress((void**)&E1,    g_E1);
    cudaGetSymbolAddress((void**)&spill, g_spill);
    cudaGetSymbolAddress((void**)&att,   g_att);
    cudaGetSymbolAddress((void**)&red,   g_red);
    cudaGetSymbolAddress((void**)&part,  g_part);
    cudaGetSymbolAddress((void**)&tI,    g_tI);
    cudaGetSymbolAddress((void**)&tP,    g_tP);
    cudaGetSymbolAddress((void**)&Xbf,   g_Xbf);
    cudaGetSymbolAddress((void**)&h1b,   g_h1b);
    cudaGetSymbolAddress((void**)&hb,    g_hb);
    cudaGetSymbolAddress((void**)&ehs,   g_ehs);
    cudaGetSymbolAddress((void**)&ets,   g_ets);
    cudaGetSymbolAddress((void**)&Ub,    g_Ub);
    cudaGetSymbolAddress((void**)&Vb,    g_Vb);
    cudaGetSymbolAddress((void**)&Wfc1b, g_Wfc1b);
    cudaGetSymbolAddress((void**)&Wfc2b, g_Wfc2b);
    cudaGetSymbolAddress((void**)&Whdb,  g_Whdb);
    cudaGetSymbolAddress((void**)&Wtlb,  g_Wtlb);
    cudaGetSymbolAddress((void**)&Wl1b,  g_Wl1b);
    cudaGetSymbolAddress((void**)&Wl2b,  g_Wl2b);

    const int smemNeed = 3 * MMA_STG;
    cudaFuncSetAttribute(attn_mma_kernel,
                         cudaFuncAttributeMaxDynamicSharedMemorySize, smemNeed);
    cudaFuncSetAttribute(mma_gemm_kernel<1, true,  false>,
                         cudaFuncAttributeMaxDynamicSharedMemorySize, smemNeed);
    cudaFuncSetAttribute(mma_gemm_kernel<2, false, false>,
                         cudaFuncAttributeMaxDynamicSharedMemorySize, smemNeed);
    cudaFuncSetAttribute(mma_gemm_kernel<3, false, false>,
                         cudaFuncAttributeMaxDynamicSharedMemorySize, smemNeed);
    cudaFuncSetAttribute(mma_gemm_kernel<0, true,  false>,
                         cudaFuncAttributeMaxDynamicSharedMemorySize, smemNeed);
    cudaFuncSetAttribute(mma_gemm_kernel<0, true,  true>,
                         cudaFuncAttributeMaxDynamicSharedMemorySize, smemNeed);

    float* out = (float*)d_out;
    const size_t ND = (size_t)NN_ * DD_;
    float* e_out;
    float* eg_out;
    if ((size_t)out_size >= ND + DD_)      { e_out = out;   eg_out = out + ND; }
    else if ((size_t)out_size >= ND)       { e_out = out;   eg_out = nullptr;  }
    else                                   { e_out = spill; eg_out = out;      }

    const dim3 gG(2, 64);
    const dim3 gA(64, 64);

    xsplit_kernel<<<NN_, 256>>>(x, Xbf);
    wprep6_kernel<<<DIN_ + 5 * DD_, 256>>>(Wfc1, Wfc2, Whd, Wtl, Wl1, Wl2,
                                           Wfc1b, Wfc2b, Whdb, Wtlb, Wl1b, Wl2b);

    mma_gemm_kernel<1, true,  false><<<gG, 512, smemNeed>>>(Xbf, Wfc1b, bfc1, nullptr, nullptr, h1b, KAX_, 0.f);
    mma_gemm_kernel<1, true,  false><<<gG, 512, smemNeed>>>(h1b, Wfc2b, bfc2, nullptr, nullptr, hb,  KA4_, 0.f);
    mma_gemm_kernel<2, false, false><<<gG, 512, smemNeed>>>(hb,  Whdb,  bhd,  nullptr, eh,      ehs, KA4_, 0.0625f);
    mma_gemm_kernel<3, false, false><<<gG, 512, smemNeed>>>(hb,  Wtlb,  btl,  nullptr, et,      ets, KA4_, 0.f);

    attn_mma_kernel<<<gA, 256, smemNeed>>>(ehs, ets, P);
    topk_kernel    <<<NN_, 256>>>(P, tI, tP);
    neighbor_kernel<<<NN_, 256>>>(eh, et, tI, tP, Ub, Vb);

    mma_gemm_kernel<0, true, false><<<gG, 512, smemNeed>>>(Ub, Wl1b, bl1, nullptr, E1,    nullptr, KA4_, 0.f);
    mma_gemm_kernel<0, true, true ><<<gG, 512, smemNeed>>>(Vb, Wl2b, bl2, E1,      e_out, nullptr, KA4_, 0.f);

    if (eg_out) {
        att_kernel   <<<NN_ / 16, 128>>>(e_out, Wa1, ba1, Wa2, ba2, att);
        smred_kernel <<<1, 1024>>>(att, red);
        egpart_kernel<<<32, 256>>>(att, e_out, red, part);
        egfin_kernel <<<1, 256>>>(part, red, eg_out);
    }
}